// round 10
// baseline (speedup 1.0000x reference)
#include <cuda_runtime.h>
#include <cuda_bf16.h>
#include <math.h>
#include <stdint.h>

#define MSG_DIM 100
#define MEM_DIM 172
#define KDIM    272
#define JPAD    176
#define MROWS   128            // update rows per CTA
#define NTH     256
#define KSTEPS  17             // 272 / 16
#define NJC     22             // 176 / 8 col-chunks
#define XSTR    280            // bf16 elems per x row (560 B, bank-clean LDSM stride)
#define NTILE   (NJC * 4 * 2 * KSTEPS)   // 2992 weight-fragment tiles

// ---------------- persistent scratch ----------------
// B fragments pre-packed in mma.m16n8k16 register layout:
// tile = ((jc*4 + plane)*2 + split)*17 + ks ; per tile: 32 lanes x uint2.
// plane: 0=r, 1=z, 2=i_n (k<100, zero-padded), 3=h_n (k>=100, zero-padded)
__device__ __align__(16) uint2 g_Wf[(size_t)NTILE * 32];
__device__ float g_bias[4 * JPAD];   // br, bz, bi, bh

// ---------------- smem layout (bytes) ----------------
#define SM_NID 0
#define SM_TS  512
#define SM_XH  1024
#define SM_XL  (SM_XH + MROWS * XSTR * 2)     // 72704
#define SM_TOT (SM_XL + MROWS * XSTR * 2)     // 144384

// ---------------- helpers ----------------
__device__ __forceinline__ uint32_t smem_u32(const void* p) {
    uint32_t a;
    asm("{ .reg .u64 t; cvta.to.shared.u64 t, %1; cvt.u32.u64 %0, t; }" : "=r"(a) : "l"(p));
    return a;
}
#define LDSM4(r0, r1, r2, r3, addr) \
    asm volatile("ldmatrix.sync.aligned.m8n8.x4.shared.b16 {%0,%1,%2,%3}, [%4];" \
                 : "=r"(r0), "=r"(r1), "=r"(r2), "=r"(r3) : "r"(addr))
#define MMA(d, a0, a1, a2, a3, b) \
    asm volatile("mma.sync.aligned.m16n8k16.row.col.f32.bf16.bf16.f32 " \
                 "{%0,%1,%2,%3}, {%4,%5,%6,%7}, {%8,%9}, {%0,%1,%2,%3};" \
                 : "+f"((d)[0]), "+f"((d)[1]), "+f"((d)[2]), "+f"((d)[3]) \
                 : "r"(a0), "r"(a1), "r"(a2), "r"(a3), "r"((b).x), "r"((b).y))

__device__ __forceinline__ float wval(int plane, int n, int k,
                                      const float* __restrict__ W_ih,
                                      const float* __restrict__ W_hh) {
    if (n >= MEM_DIM || k >= KDIM) return 0.f;
    if (plane == 0)
        return (k < MSG_DIM) ? W_ih[n * MSG_DIM + k]
                             : W_hh[n * MEM_DIM + (k - MSG_DIM)];
    if (plane == 1)
        return (k < MSG_DIM) ? W_ih[(MEM_DIM + n) * MSG_DIM + k]
                             : W_hh[(MEM_DIM + n) * MEM_DIM + (k - MSG_DIM)];
    if (plane == 2)
        return (k < MSG_DIM) ? W_ih[(2 * MEM_DIM + n) * MSG_DIM + k] : 0.f;
    return (k >= MSG_DIM) ? W_hh[(2 * MEM_DIM + n) * MEM_DIM + (k - MSG_DIM)] : 0.f;
}
__device__ __forceinline__ float bf_split(float w, int split) {
    __nv_bfloat16 h = __float2bfloat16(w);
    if (split == 0) return __bfloat162float(h);
    return w - __bfloat162float(h);       // rounded to bf16 at pack time
}
__device__ __forceinline__ uint32_t pack_bf(float a, float b) {
    __nv_bfloat162 v = __floats2bfloat162_rn(a, b);
    return *(uint32_t*)&v;                // low 16 = a
}

// ---------------------------------------------------------------------------
// Prep: build B fragments (register layout) + bias.
//   b0 -> (k = kb, kb+1), b1 -> (k = kb+8, kb+9), kb = ks*16 + (lane&3)*2
//   n = jc*8 + (lane>>2)
// ---------------------------------------------------------------------------
__global__ void prep_kernel(const float* __restrict__ W_ih,
                            const float* __restrict__ W_hh,
                            const float* __restrict__ b_ih,
                            const float* __restrict__ b_hh) {
    int idx = blockIdx.x * blockDim.x + threadIdx.x;
    if (idx < NTILE * 32) {
        int lane = idx & 31;
        int tile = idx >> 5;
        int ks    = tile % KSTEPS;
        int split = (tile / KSTEPS) & 1;
        int plane = (tile / (2 * KSTEPS)) & 3;
        int jc    = tile / (8 * KSTEPS);
        int n  = jc * 8 + (lane >> 2);
        int kb = ks * 16 + (lane & 3) * 2;
        float w00 = bf_split(wval(plane, n, kb + 0, W_ih, W_hh), split);
        float w01 = bf_split(wval(plane, n, kb + 1, W_ih, W_hh), split);
        float w10 = bf_split(wval(plane, n, kb + 8, W_ih, W_hh), split);
        float w11 = bf_split(wval(plane, n, kb + 9, W_ih, W_hh), split);
        g_Wf[(size_t)tile * 32 + lane] = make_uint2(pack_bf(w00, w01), pack_bf(w10, w11));
    }
    if (idx < JPAD) {
        int j = idx;
        float br = 0.f, bz = 0.f, bi = 0.f, bh = 0.f;
        if (j < MEM_DIM) {
            br = b_ih[j]               + b_hh[j];
            bz = b_ih[MEM_DIM + j]     + b_hh[MEM_DIM + j];
            bi = b_ih[2 * MEM_DIM + j];
            bh = b_hh[2 * MEM_DIM + j];
        }
        g_bias[j]            = br;
        g_bias[JPAD + j]     = bz;
        g_bias[2 * JPAD + j] = bi;
        g_bias[3 * JPAD + j] = bh;
    }
}

// ---------------------------------------------------------------------------
// Passthrough copy (one float4/thread; near-HBM-peak).
// ---------------------------------------------------------------------------
__global__ void copy_kernel(const float* __restrict__ src, float* __restrict__ dst, long long n) {
    long long i = (long long)blockIdx.x * blockDim.x + threadIdx.x;
    long long n4 = n >> 2;
    if (i < n4) ((float4*)dst)[i] = ((const float4*)src)[i];
    long long tail = n & 3;
    if (i < tail) dst[n4 * 4 + i] = src[n4 * 4 + i];
}

// ---------------------------------------------------------------------------
// GRU via mma.sync bf16 3-pass split. CTA = 128 rows, 8 warps (16 rows each).
// ---------------------------------------------------------------------------
__global__ void __launch_bounds__(NTH, 1)
gru_mma_kernel(const int*   __restrict__ node_ids,
               const float* __restrict__ messages,
               const float* __restrict__ timestamps,
               const float* __restrict__ memory,
               float*       __restrict__ out,
               int n_upd, long long n_nodes)
{
    extern __shared__ __align__(16) char smc[];
    int*   s_nid = (int*)(smc + SM_NID);
    float* s_ts  = (float*)(smc + SM_TS);
    __nv_bfloat16* xh = (__nv_bfloat16*)(smc + SM_XH);
    __nv_bfloat16* xl = (__nv_bfloat16*)(smc + SM_XL);
    const uint32_t smb = smem_u32(smc);

    const int tid  = threadIdx.x;
    const int lane = tid & 31;
    const int row0 = blockIdx.x * MROWS;

    if (tid < MROWS) {
        int r = row0 + tid;
        if (r < n_upd) { s_nid[tid] = node_ids[r]; s_ts[tid] = timestamps[r]; }
        else           { s_nid[tid] = -1;          s_ts[tid] = 0.f; }
    }
    __syncthreads();

    // last_update scatter
    if (tid < MROWS && s_nid[tid] >= 0)
        out[n_nodes * (long long)MEM_DIM + s_nid[tid]] = s_ts[tid];

    // ---- gather x rows, split to bf16 hi/lo ----
    for (int idx = tid; idx < MROWS * (XSTR / 2); idx += NTH) {
        int r  = idx / (XSTR / 2);
        int k  = (idx - r * (XSTR / 2)) * 2;
        float x0 = 0.f, x1 = 0.f;
        int nid = s_nid[r];
        if (nid >= 0) {
            long long grow = row0 + r;
            if (k < MSG_DIM)    x0 = messages[grow * MSG_DIM + k];
            else if (k < KDIM)  x0 = memory[(size_t)nid * MEM_DIM + (k - MSG_DIM)];
            int k1 = k + 1;
            if (k1 < MSG_DIM)   x1 = messages[grow * MSG_DIM + k1];
            else if (k1 < KDIM) x1 = memory[(size_t)nid * MEM_DIM + (k1 - MSG_DIM)];
        }
        __nv_bfloat16 h0 = __float2bfloat16(x0), h1 = __float2bfloat16(x1);
        float l0 = x0 - __bfloat162float(h0);
        float l1 = x1 - __bfloat162float(h1);
        ((uint32_t*)(xh))[idx] = ((uint32_t)__bfloat16_as_ushort(h1) << 16) |
                                 __bfloat16_as_ushort(h0);
        ((uint32_t*)(xl))[idx] = pack_bf(l0, l1);
    }
    __syncthreads();

    // ---- per-warp MMA main loop ----
    const int R  = (tid >> 5) * 16;         // this warp's row base
    const int g  = lane >> 2;
    const int tg = lane & 3;
    const uint32_t ah_base = smb + SM_XH + (R + (lane & 15)) * (XSTR * 2) + ((lane >> 4) * 16);
    const uint32_t al_base = smb + SM_XL + (R + (lane & 15)) * (XSTR * 2) + ((lane >> 4) * 16);
    const uint2* __restrict__ Wf = g_Wf;

    for (int jc = 0; jc < NJC; jc++) {
        float aR[4] = {0.f, 0.f, 0.f, 0.f};
        float aZ[4] = {0.f, 0.f, 0.f, 0.f};
        float aI[4] = {0.f, 0.f, 0.f, 0.f};
        float aH[4] = {0.f, 0.f, 0.f, 0.f};
        const int tb = jc * (8 * KSTEPS);    // 8 plane-split tiles per ks

        #pragma unroll 1
        for (int ks = 0; ks < KSTEPS; ks++) {
            uint32_t h0, h1, h2, h3, l0, l1, l2, l3;
            LDSM4(h0, h1, h2, h3, ah_base + ks * 32);
            LDSM4(l0, l1, l2, l3, al_base + ks * 32);

            const size_t o = (size_t)(tb + ks) * 32 + lane;
            uint2 bRh = Wf[o];
            uint2 bRl = Wf[o + (size_t)KSTEPS * 32];
            uint2 bZh = Wf[o + (size_t)2 * KSTEPS * 32];
            uint2 bZl = Wf[o + (size_t)3 * KSTEPS * 32];
            uint2 bIh = Wf[o + (size_t)4 * KSTEPS * 32];
            uint2 bIl = Wf[o + (size_t)5 * KSTEPS * 32];
            uint2 bHh = Wf[o + (size_t)6 * KSTEPS * 32];
            uint2 bHl = Wf[o + (size_t)7 * KSTEPS * 32];

            const bool doI = (ks < 7);       // k < 112 (W zero-padded past 100)
            const bool doH = (ks >= 6);      // k >= 96 (W zero-padded before 100)

            // pass 1: Wh * xh
            MMA(aR, h0, h1, h2, h3, bRh);
            MMA(aZ, h0, h1, h2, h3, bZh);
            if (doI) MMA(aI, h0, h1, h2, h3, bIh);
            if (doH) MMA(aH, h0, h1, h2, h3, bHh);
            // pass 2: Wh * xl
            MMA(aR, l0, l1, l2, l3, bRh);
            MMA(aZ, l0, l1, l2, l3, bZh);
            if (doI) MMA(aI, l0, l1, l2, l3, bIh);
            if (doH) MMA(aH, l0, l1, l2, l3, bHh);
            // pass 3: Wl * xh
            MMA(aR, h0, h1, h2, h3, bRl);
            MMA(aZ, h0, h1, h2, h3, bZl);
            if (doI) MMA(aI, h0, h1, h2, h3, bIl);
            if (doH) MMA(aH, h0, h1, h2, h3, bHl);
        }

        // ---- epilogue for this (warp, jc): gates fully resident ----
        #pragma unroll
        for (int e = 0; e < 4; e++) {
            int lr = R + g + (e >> 1) * 8;       // local row
            int j  = jc * 8 + tg * 2 + (e & 1);  // output column
            int nid = s_nid[lr];
            if (nid >= 0 && j < MEM_DIM) {
                float Rv = aR[e] + g_bias[j];
                float Zv = aZ[e] + g_bias[JPAD + j];
                float Iv = aI[e] + g_bias[2 * JPAD + j];
                float Hv = aH[e] + g_bias[3 * JPAD + j];
                int kk = MSG_DIM + j;
                float h_old = __bfloat162float(xh[lr * XSTR + kk]) +
                              __bfloat162float(xl[lr * XSTR + kk]);
                float rg = 1.f / (1.f + expf(-Rv));
                float zg = 1.f / (1.f + expf(-Zv));
                float ng = tanhf(Iv + rg * Hv);
                out[(size_t)nid * MEM_DIM + j] = (1.f - zg) * ng + zg * h_old;
            }
        }
    }
}

// ---------------------------------------------------------------------------
extern "C" void kernel_launch(void* const* d_in, const int* in_sizes, int n_in,
                              void* d_out, int out_size) {
    const int*   node_ids    = (const int*)  d_in[0];
    const float* messages    = (const float*)d_in[1];
    const float* timestamps  = (const float*)d_in[2];
    const float* memory      = (const float*)d_in[3];
    const float* last_update = (const float*)d_in[4];
    const float* W_ih        = (const float*)d_in[5];
    const float* W_hh        = (const float*)d_in[6];
    const float* b_ih        = (const float*)d_in[7];
    const float* b_hh        = (const float*)d_in[8];
    float* out = (float*)d_out;

    const int       n_upd   = in_sizes[0];
    const long long n_nodes = in_sizes[4];
    const long long nmem    = n_nodes * (long long)MEM_DIM;

    cudaFuncSetAttribute(gru_mma_kernel,
                         cudaFuncAttributeMaxDynamicSharedMemorySize, SM_TOT);

    prep_kernel<<<(NTILE * 32 + 255) / 256, 256>>>(W_ih, W_hh, b_ih, b_hh);

    {
        long long n4 = (nmem + 3) >> 2;
        copy_kernel<<<(unsigned)((n4 + 255) / 256), 256>>>(memory, out, nmem);
        long long n4b = (n_nodes + 3) >> 2;
        copy_kernel<<<(unsigned)((n4b + 255) / 256), 256>>>(last_update, out + nmem, n_nodes);
    }

    if (n_upd > 0) {
        gru_mma_kernel<<<(n_upd + MROWS - 1) / MROWS, NTH, SM_TOT>>>(
            node_ids, messages, timestamps, memory, out, n_upd, n_nodes);
    }
}

// round 11
// speedup vs baseline: 1.3284x; 1.3284x over previous
#include <cuda_runtime.h>
#include <cuda_bf16.h>
#include <math.h>
#include <stdint.h>

#define MSG_DIM 100
#define MEM_DIM 172
#define KDIM    272
#define JPAD    176
#define MROWS   64             // update rows per CTA
#define NTH     128
#define KSTEPS  17             // 272 / 16
#define NJC     22             // 176 / 8 col-chunks
#define XSTR    280            // bf16 elems per x row (560 B)
#define NTILE   (NJC * 4 * 2 * KSTEPS)   // 2992 weight-fragment tiles

// ---------------- persistent scratch ----------------
// B fragments pre-packed in mma.m16n8k16 register layout:
// tile = ((jc*4 + plane)*2 + split)*17 + ks ; per tile: 32 lanes x uint2.
// plane: 0=r, 1=z, 2=i_n (k<100, zero-padded), 3=h_n (k>=100, zero-padded)
__device__ __align__(16) uint2 g_Wf[(size_t)NTILE * 32];
__device__ float g_bias[4 * JPAD];   // br, bz, bi, bh

// ---------------- smem layout (bytes) ----------------
#define SM_NID 0
#define SM_TS  256
#define SM_XH  1024
#define SM_XL  (SM_XH + MROWS * XSTR * 2)     // 36864
#define SM_TOT (SM_XL + MROWS * XSTR * 2)     // 72704 -> 3 CTAs/SM

// ---------------- helpers ----------------
__device__ __forceinline__ uint32_t smem_u32(const void* p) {
    uint32_t a;
    asm("{ .reg .u64 t; cvta.to.shared.u64 t, %1; cvt.u32.u64 %0, t; }" : "=r"(a) : "l"(p));
    return a;
}
#define LDSM4(r0, r1, r2, r3, addr) \
    asm volatile("ldmatrix.sync.aligned.m8n8.x4.shared.b16 {%0,%1,%2,%3}, [%4];" \
                 : "=r"(r0), "=r"(r1), "=r"(r2), "=r"(r3) : "r"(addr))
#define MMA(d, a0, a1, a2, a3, b) \
    asm volatile("mma.sync.aligned.m16n8k16.row.col.f32.bf16.bf16.f32 " \
                 "{%0,%1,%2,%3}, {%4,%5,%6,%7}, {%8,%9}, {%0,%1,%2,%3};" \
                 : "+f"((d)[0]), "+f"((d)[1]), "+f"((d)[2]), "+f"((d)[3]) \
                 : "r"(a0), "r"(a1), "r"(a2), "r"(a3), "r"((b).x), "r"((b).y))

__device__ __forceinline__ float wval(int plane, int n, int k,
                                      const float* __restrict__ W_ih,
                                      const float* __restrict__ W_hh) {
    if (n >= MEM_DIM || k >= KDIM) return 0.f;
    if (plane == 0)
        return (k < MSG_DIM) ? W_ih[n * MSG_DIM + k]
                             : W_hh[n * MEM_DIM + (k - MSG_DIM)];
    if (plane == 1)
        return (k < MSG_DIM) ? W_ih[(MEM_DIM + n) * MSG_DIM + k]
                             : W_hh[(MEM_DIM + n) * MEM_DIM + (k - MSG_DIM)];
    if (plane == 2)
        return (k < MSG_DIM) ? W_ih[(2 * MEM_DIM + n) * MSG_DIM + k] : 0.f;
    return (k >= MSG_DIM) ? W_hh[(2 * MEM_DIM + n) * MEM_DIM + (k - MSG_DIM)] : 0.f;
}
__device__ __forceinline__ float bf_split(float w, int split) {
    __nv_bfloat16 h = __float2bfloat16(w);
    if (split == 0) return __bfloat162float(h);
    return w - __bfloat162float(h);
}
__device__ __forceinline__ uint32_t pack_bf(float a, float b) {
    __nv_bfloat162 v = __floats2bfloat162_rn(a, b);
    return *(uint32_t*)&v;                // low 16 = a
}

// ---------------------------------------------------------------------------
// Prep: build B fragments (register layout) + bias. (Unchanged from R10.)
// ---------------------------------------------------------------------------
__global__ void prep_kernel(const float* __restrict__ W_ih,
                            const float* __restrict__ W_hh,
                            const float* __restrict__ b_ih,
                            const float* __restrict__ b_hh) {
    int idx = blockIdx.x * blockDim.x + threadIdx.x;
    if (idx < NTILE * 32) {
        int lane = idx & 31;
        int tile = idx >> 5;
        int ks    = tile % KSTEPS;
        int split = (tile / KSTEPS) & 1;
        int plane = (tile / (2 * KSTEPS)) & 3;
        int jc    = tile / (8 * KSTEPS);
        int n  = jc * 8 + (lane >> 2);
        int kb = ks * 16 + (lane & 3) * 2;
        float w00 = bf_split(wval(plane, n, kb + 0, W_ih, W_hh), split);
        float w01 = bf_split(wval(plane, n, kb + 1, W_ih, W_hh), split);
        float w10 = bf_split(wval(plane, n, kb + 8, W_ih, W_hh), split);
        float w11 = bf_split(wval(plane, n, kb + 9, W_ih, W_hh), split);
        g_Wf[(size_t)tile * 32 + lane] = make_uint2(pack_bf(w00, w01), pack_bf(w10, w11));
    }
    if (idx < JPAD) {
        int j = idx;
        float br = 0.f, bz = 0.f, bi = 0.f, bh = 0.f;
        if (j < MEM_DIM) {
            br = b_ih[j]               + b_hh[j];
            bz = b_ih[MEM_DIM + j]     + b_hh[MEM_DIM + j];
            bi = b_ih[2 * MEM_DIM + j];
            bh = b_hh[2 * MEM_DIM + j];
        }
        g_bias[j]            = br;
        g_bias[JPAD + j]     = bz;
        g_bias[2 * JPAD + j] = bi;
        g_bias[3 * JPAD + j] = bh;
    }
}

// ---------------------------------------------------------------------------
// Passthrough copy (one float4/thread; near-HBM-peak).
// ---------------------------------------------------------------------------
__global__ void copy_kernel(const float* __restrict__ src, float* __restrict__ dst, long long n) {
    long long i = (long long)blockIdx.x * blockDim.x + threadIdx.x;
    long long n4 = n >> 2;
    if (i < n4) ((float4*)dst)[i] = ((const float4*)src)[i];
    long long tail = n & 3;
    if (i < tail) dst[n4 * 4 + i] = src[n4 * 4 + i];
}

// ---------------------------------------------------------------------------
// GRU via mma.sync bf16 3-pass split. CTA = 64 rows, 4 warps (16 rows each),
// 3 CTAs/SM. Each warp processes 2 jc chunks per pass (8 accum chains).
// ---------------------------------------------------------------------------
__global__ void __launch_bounds__(NTH, 3)
gru_mma_kernel(const int*   __restrict__ node_ids,
               const float* __restrict__ messages,
               const float* __restrict__ timestamps,
               const float* __restrict__ memory,
               float*       __restrict__ out,
               int n_upd, long long n_nodes)
{
    extern __shared__ __align__(16) char smc[];
    int*   s_nid = (int*)(smc + SM_NID);
    float* s_ts  = (float*)(smc + SM_TS);
    __nv_bfloat16* xh = (__nv_bfloat16*)(smc + SM_XH);
    __nv_bfloat16* xl = (__nv_bfloat16*)(smc + SM_XL);
    const uint32_t smb = smem_u32(smc);

    const int tid  = threadIdx.x;
    const int lane = tid & 31;
    const int row0 = blockIdx.x * MROWS;

    if (tid < MROWS) {
        int r = row0 + tid;
        if (r < n_upd) { s_nid[tid] = node_ids[r]; s_ts[tid] = timestamps[r]; }
        else           { s_nid[tid] = -1;          s_ts[tid] = 0.f; }
    }
    __syncthreads();

    // last_update scatter
    if (tid < MROWS && s_nid[tid] >= 0)
        out[n_nodes * (long long)MEM_DIM + s_nid[tid]] = s_ts[tid];

    // ---- gather x rows, split to bf16 hi/lo ----
    for (int idx = tid; idx < MROWS * (XSTR / 2); idx += NTH) {
        int r  = idx / (XSTR / 2);
        int k  = (idx - r * (XSTR / 2)) * 2;
        float x0 = 0.f, x1 = 0.f;
        int nid = s_nid[r];
        if (nid >= 0) {
            long long grow = row0 + r;
            if (k < MSG_DIM)    x0 = messages[grow * MSG_DIM + k];
            else if (k < KDIM)  x0 = memory[(size_t)nid * MEM_DIM + (k - MSG_DIM)];
            int k1 = k + 1;
            if (k1 < MSG_DIM)   x1 = messages[grow * MSG_DIM + k1];
            else if (k1 < KDIM) x1 = memory[(size_t)nid * MEM_DIM + (k1 - MSG_DIM)];
        }
        __nv_bfloat16 h0 = __float2bfloat16(x0), h1 = __float2bfloat16(x1);
        float l0 = x0 - __bfloat162float(h0);
        float l1 = x1 - __bfloat162float(h1);
        ((uint32_t*)(xh))[idx] = ((uint32_t)__bfloat16_as_ushort(h1) << 16) |
                                 __bfloat16_as_ushort(h0);
        ((uint32_t*)(xl))[idx] = pack_bf(l0, l1);
    }
    __syncthreads();

    // ---- per-warp MMA main loop: 2 jc chunks per pass ----
    const int R  = (tid >> 5) * 16;         // this warp's row base
    const int g  = lane >> 2;
    const int tg = lane & 3;
    const uint32_t ah_base = smb + SM_XH + (R + (lane & 15)) * (XSTR * 2) + ((lane >> 4) * 16);
    const uint32_t al_base = smb + SM_XL + (R + (lane & 15)) * (XSTR * 2) + ((lane >> 4) * 16);
    const uint2* __restrict__ Wf = g_Wf;

    for (int jp = 0; jp < NJC / 2; jp++) {
        float aR[2][4] = {}, aZ[2][4] = {}, aI[2][4] = {}, aH[2][4] = {};
        const int tb0 = (jp * 2 + 0) * (8 * KSTEPS);
        const int tb1 = (jp * 2 + 1) * (8 * KSTEPS);

        #pragma unroll 1
        for (int ks = 0; ks < KSTEPS; ks++) {
            uint32_t h0, h1, h2, h3, l0, l1, l2, l3;
            LDSM4(h0, h1, h2, h3, ah_base + ks * 32);
            LDSM4(l0, l1, l2, l3, al_base + ks * 32);

            const bool doI = (ks < 7);       // k < 112 (zero-padded past 100)
            const bool doH = (ks >= 6);      // k >= 96 (zero-padded before 100)

            #pragma unroll
            for (int u = 0; u < 2; u++) {
                const size_t o = (size_t)((u ? tb1 : tb0) + ks) * 32 + lane;
                uint2 bRh = Wf[o];
                uint2 bRl = Wf[o + (size_t)KSTEPS * 32];
                uint2 bZh = Wf[o + (size_t)2 * KSTEPS * 32];
                uint2 bZl = Wf[o + (size_t)3 * KSTEPS * 32];
                uint2 bIh = Wf[o + (size_t)4 * KSTEPS * 32];
                uint2 bIl = Wf[o + (size_t)5 * KSTEPS * 32];
                uint2 bHh = Wf[o + (size_t)6 * KSTEPS * 32];
                uint2 bHl = Wf[o + (size_t)7 * KSTEPS * 32];

                // pass 1: Wh * xh
                MMA(aR[u], h0, h1, h2, h3, bRh);
                MMA(aZ[u], h0, h1, h2, h3, bZh);
                if (doI) MMA(aI[u], h0, h1, h2, h3, bIh);
                if (doH) MMA(aH[u], h0, h1, h2, h3, bHh);
                // pass 2: Wh * xl
                MMA(aR[u], l0, l1, l2, l3, bRh);
                MMA(aZ[u], l0, l1, l2, l3, bZh);
                if (doI) MMA(aI[u], l0, l1, l2, l3, bIh);
                if (doH) MMA(aH[u], l0, l1, l2, l3, bHh);
                // pass 3: Wl * xh
                MMA(aR[u], h0, h1, h2, h3, bRl);
                MMA(aZ[u], h0, h1, h2, h3, bZl);
                if (doI) MMA(aI[u], h0, h1, h2, h3, bIl);
                if (doH) MMA(aH[u], h0, h1, h2, h3, bHl);
            }
        }

        // ---- epilogue for both jc chunks ----
        #pragma unroll
        for (int u = 0; u < 2; u++) {
            const int jc = jp * 2 + u;
            #pragma unroll
            for (int e = 0; e < 4; e++) {
                int lr = R + g + (e >> 1) * 8;       // local row
                int j  = jc * 8 + tg * 2 + (e & 1);  // output column
                int nid = s_nid[lr];
                if (nid >= 0 && j < MEM_DIM) {
                    float Rv = aR[u][e] + g_bias[j];
                    float Zv = aZ[u][e] + g_bias[JPAD + j];
                    float Iv = aI[u][e] + g_bias[2 * JPAD + j];
                    float Hv = aH[u][e] + g_bias[3 * JPAD + j];
                    int kk = MSG_DIM + j;
                    float h_old = __bfloat162float(xh[lr * XSTR + kk]) +
                                  __bfloat162float(xl[lr * XSTR + kk]);
                    float rg = 1.f / (1.f + expf(-Rv));
                    float zg = 1.f / (1.f + expf(-Zv));
                    float ng = tanhf(Iv + rg * Hv);
                    out[(size_t)nid * MEM_DIM + j] = (1.f - zg) * ng + zg * h_old;
                }
            }
        }
    }
}

// ---------------------------------------------------------------------------
extern "C" void kernel_launch(void* const* d_in, const int* in_sizes, int n_in,
                              void* d_out, int out_size) {
    const int*   node_ids    = (const int*)  d_in[0];
    const float* messages    = (const float*)d_in[1];
    const float* timestamps  = (const float*)d_in[2];
    const float* memory      = (const float*)d_in[3];
    const float* last_update = (const float*)d_in[4];
    const float* W_ih        = (const float*)d_in[5];
    const float* W_hh        = (const float*)d_in[6];
    const float* b_ih        = (const float*)d_in[7];
    const float* b_hh        = (const float*)d_in[8];
    float* out = (float*)d_out;

    const int       n_upd   = in_sizes[0];
    const long long n_nodes = in_sizes[4];
    const long long nmem    = n_nodes * (long long)MEM_DIM;

    cudaFuncSetAttribute(gru_mma_kernel,
                         cudaFuncAttributeMaxDynamicSharedMemorySize, SM_TOT);

    prep_kernel<<<(NTILE * 32 + 255) / 256, 256>>>(W_ih, W_hh, b_ih, b_hh);

    {
        long long n4 = (nmem + 3) >> 2;
        copy_kernel<<<(unsigned)((n4 + 255) / 256), 256>>>(memory, out, nmem);
        long long n4b = (n_nodes + 3) >> 2;
        copy_kernel<<<(unsigned)((n4b + 255) / 256), 256>>>(last_update, out + nmem, n_nodes);
    }

    if (n_upd > 0) {
        gru_mma_kernel<<<(n_upd + MROWS - 1) / MROWS, NTH, SM_TOT>>>(
            node_ids, messages, timestamps, memory, out, n_upd, n_nodes);
    }
}

// round 12
// speedup vs baseline: 1.6808x; 1.2653x over previous
#include <cuda_runtime.h>
#include <cuda_bf16.h>
#include <math.h>
#include <stdint.h>

#define MSG_DIM 100
#define MEM_DIM 172
#define KDIM    272
#define JPAD    176
#define MROWS   64             // update rows per CTA
#define NTH     128
#define KSTEPS  17             // 272 / 16
#define NJC     22             // 176 / 8 col-chunks
#define NJW     11             // jc chunks per warp (jc-half)
#define XSTR    280            // bf16 elems per x row (560 B)
// fragment tiles: (jc, ks) x 4 pair-slots x 32 lanes of uint4
#define NFRAG   (NJC * KSTEPS * 4 * 32)

// ---------------- persistent scratch ----------------
// uint4 = two gate fragments: p=0:{Rh,Zh} p=1:{Ih,Hh} p=2:{Rl,Zl} p=3:{Il,Hl}
__device__ __align__(16) uint4 g_Wf[NFRAG];
__device__ float g_bias[4 * JPAD];   // br, bz, bi, bh

// ---------------- smem layout (bytes) ----------------
#define SM_NID 0
#define SM_TS  256
#define SM_XH  1024
#define SM_XL  (SM_XH + MROWS * XSTR * 2)     // 36864
#define SM_TOT (SM_XL + MROWS * XSTR * 2)     // 72704 -> 3 CTAs/SM

// ---------------- helpers ----------------
__device__ __forceinline__ uint32_t smem_u32(const void* p) {
    uint32_t a;
    asm("{ .reg .u64 t; cvta.to.shared.u64 t, %1; cvt.u32.u64 %0, t; }" : "=r"(a) : "l"(p));
    return a;
}
#define LDSM4(r0, r1, r2, r3, addr) \
    asm volatile("ldmatrix.sync.aligned.m8n8.x4.shared.b16 {%0,%1,%2,%3}, [%4];" \
                 : "=r"(r0), "=r"(r1), "=r"(r2), "=r"(r3) : "r"(addr))
#define MMA(d, a, b0, b1) \
    asm volatile("mma.sync.aligned.m16n8k16.row.col.f32.bf16.bf16.f32 " \
                 "{%0,%1,%2,%3}, {%4,%5,%6,%7}, {%8,%9}, {%0,%1,%2,%3};" \
                 : "+f"((d)[0]), "+f"((d)[1]), "+f"((d)[2]), "+f"((d)[3]) \
                 : "r"((a)[0]), "r"((a)[1]), "r"((a)[2]), "r"((a)[3]), \
                   "r"(b0), "r"(b1))

__device__ __forceinline__ float wval(int plane, int n, int k,
                                      const float* __restrict__ W_ih,
                                      const float* __restrict__ W_hh) {
    if (n >= MEM_DIM || k >= KDIM) return 0.f;
    if (plane == 0)
        return (k < MSG_DIM) ? W_ih[n * MSG_DIM + k]
                             : W_hh[n * MEM_DIM + (k - MSG_DIM)];
    if (plane == 1)
        return (k < MSG_DIM) ? W_ih[(MEM_DIM + n) * MSG_DIM + k]
                             : W_hh[(MEM_DIM + n) * MEM_DIM + (k - MSG_DIM)];
    if (plane == 2)
        return (k < MSG_DIM) ? W_ih[(2 * MEM_DIM + n) * MSG_DIM + k] : 0.f;
    return (k >= MSG_DIM) ? W_hh[(2 * MEM_DIM + n) * MEM_DIM + (k - MSG_DIM)] : 0.f;
}
__device__ __forceinline__ float bf_split(float w, int split) {
    __nv_bfloat16 h = __float2bfloat16(w);
    if (split == 0) return __bfloat162float(h);
    return w - __bfloat162float(h);
}
__device__ __forceinline__ uint32_t pack_bf(float a, float b) {
    __nv_bfloat162 v = __floats2bfloat162_rn(a, b);
    return *(uint32_t*)&v;                // low 16 = a
}

// ---------------------------------------------------------------------------
// Prep: build paired B fragments (uint4 = 2 gate frags) + bias.
// Mapping per gate fragment (validated in R10):
//   n = jc*8 + (lane>>2), kb = ks*16 + (lane&3)*2
//   b0 = pack(w[kb], w[kb+1]), b1 = pack(w[kb+8], w[kb+9])
// ---------------------------------------------------------------------------
__global__ void prep_kernel(const float* __restrict__ W_ih,
                            const float* __restrict__ W_hh,
                            const float* __restrict__ b_ih,
                            const float* __restrict__ b_hh) {
    int idx = blockIdx.x * blockDim.x + threadIdx.x;
    if (idx < NFRAG) {
        int lane = idx & 31;
        int rest = idx >> 5;
        int p    = rest & 3;
        rest >>= 2;
        int ks   = rest % KSTEPS;
        int jc   = rest / KSTEPS;
        int split  = p >> 1;               // 0 = hi, 1 = lo
        int planeA = (p & 1) * 2;          // 0 (R) or 2 (I)
        int planeB = planeA + 1;           // 1 (Z) or 3 (H)
        int n  = jc * 8 + (lane >> 2);
        int kb = ks * 16 + (lane & 3) * 2;
        float a00 = bf_split(wval(planeA, n, kb + 0, W_ih, W_hh), split);
        float a01 = bf_split(wval(planeA, n, kb + 1, W_ih, W_hh), split);
        float a10 = bf_split(wval(planeA, n, kb + 8, W_ih, W_hh), split);
        float a11 = bf_split(wval(planeA, n, kb + 9, W_ih, W_hh), split);
        float b00 = bf_split(wval(planeB, n, kb + 0, W_ih, W_hh), split);
        float b01 = bf_split(wval(planeB, n, kb + 1, W_ih, W_hh), split);
        float b10 = bf_split(wval(planeB, n, kb + 8, W_ih, W_hh), split);
        float b11 = bf_split(wval(planeB, n, kb + 9, W_ih, W_hh), split);
        g_Wf[idx] = make_uint4(pack_bf(a00, a01), pack_bf(a10, a11),
                               pack_bf(b00, b01), pack_bf(b10, b11));
    }
    if (idx < JPAD) {
        int j = idx;
        float br = 0.f, bz = 0.f, bi = 0.f, bh = 0.f;
        if (j < MEM_DIM) {
            br = b_ih[j]               + b_hh[j];
            bz = b_ih[MEM_DIM + j]     + b_hh[MEM_DIM + j];
            bi = b_ih[2 * MEM_DIM + j];
            bh = b_hh[2 * MEM_DIM + j];
        }
        g_bias[j]            = br;
        g_bias[JPAD + j]     = bz;
        g_bias[2 * JPAD + j] = bi;
        g_bias[3 * JPAD + j] = bh;
    }
}

// ---------------------------------------------------------------------------
// Passthrough copy (one float4/thread; near-HBM-peak).
// ---------------------------------------------------------------------------
__global__ void copy_kernel(const float* __restrict__ src, float* __restrict__ dst, long long n) {
    long long i = (long long)blockIdx.x * blockDim.x + threadIdx.x;
    long long n4 = n >> 2;
    if (i < n4) ((float4*)dst)[i] = ((const float4*)src)[i];
    long long tail = n & 3;
    if (i < tail) dst[n4 * 4 + i] = src[n4 * 4 + i];
}

// ---------------------------------------------------------------------------
// GRU via mma.sync bf16 3-pass split. CTA = 64 rows, 4 warps, 3 CTAs/SM.
// Warp = (row-half: 32 rows = 2 m16 tiles) x (jc-half: 11 chunks).
// Each B fragment feeds 2 MMAs (row tiles); B loads are LDG.128 pairs.
// ---------------------------------------------------------------------------
__global__ void __launch_bounds__(NTH, 3)
gru_mma_kernel(const int*   __restrict__ node_ids,
               const float* __restrict__ messages,
               const float* __restrict__ timestamps,
               const float* __restrict__ memory,
               float*       __restrict__ out,
               int n_upd, long long n_nodes)
{
    extern __shared__ __align__(16) char smc[];
    int*   s_nid = (int*)(smc + SM_NID);
    float* s_ts  = (float*)(smc + SM_TS);
    __nv_bfloat16* xh = (__nv_bfloat16*)(smc + SM_XH);
    __nv_bfloat16* xl = (__nv_bfloat16*)(smc + SM_XL);
    const uint32_t smb = smem_u32(smc);

    const int tid  = threadIdx.x;
    const int lane = tid & 31;
    const int wid  = tid >> 5;
    const int row0 = blockIdx.x * MROWS;

    if (tid < MROWS) {
        int r = row0 + tid;
        if (r < n_upd) { s_nid[tid] = node_ids[r]; s_ts[tid] = timestamps[r]; }
        else           { s_nid[tid] = -1;          s_ts[tid] = 0.f; }
    }
    __syncthreads();

    // last_update scatter
    if (tid < MROWS && s_nid[tid] >= 0)
        out[n_nodes * (long long)MEM_DIM + s_nid[tid]] = s_ts[tid];

    // ---- gather x rows, split to bf16 hi/lo ----
    for (int idx = tid; idx < MROWS * (XSTR / 2); idx += NTH) {
        int r  = idx / (XSTR / 2);
        int k  = (idx - r * (XSTR / 2)) * 2;
        float x0 = 0.f, x1 = 0.f;
        int nid = s_nid[r];
        if (nid >= 0) {
            long long grow = row0 + r;
            if (k < MSG_DIM)    x0 = messages[grow * MSG_DIM + k];
            else if (k < KDIM)  x0 = memory[(size_t)nid * MEM_DIM + (k - MSG_DIM)];
            int k1 = k + 1;
            if (k1 < MSG_DIM)   x1 = messages[grow * MSG_DIM + k1];
            else if (k1 < KDIM) x1 = memory[(size_t)nid * MEM_DIM + (k1 - MSG_DIM)];
        }
        __nv_bfloat16 h0 = __float2bfloat16(x0), h1 = __float2bfloat16(x1);
        float l0 = x0 - __bfloat162float(h0);
        float l1 = x1 - __bfloat162float(h1);
        ((uint32_t*)(xh))[idx] = ((uint32_t)__bfloat16_as_ushort(h1) << 16) |
                                 __bfloat16_as_ushort(h0);
        ((uint32_t*)(xl))[idx] = pack_bf(l0, l1);
    }
    __syncthreads();

    // ---- per-warp MMA main loop ----
    const int R      = (wid & 1) * 32;           // warp's 32-row base
    const int jcbase = (wid >> 1) * NJW;         // warp's jc range
    const int g  = lane >> 2;
    const int tg = lane & 3;
    uint32_t ah[2], al[2];
    #pragma unroll
    for (int t = 0; t < 2; t++) {
        int rr = R + t * 16 + (lane & 15);
        ah[t] = smb + SM_XH + rr * (XSTR * 2) + ((lane >> 4) * 16);
        al[t] = smb + SM_XL + rr * (XSTR * 2) + ((lane >> 4) * 16);
    }

    for (int jcl = 0; jcl < NJW; jcl++) {
        const int jc = jcbase + jcl;
        float aR[2][4] = {}, aZ[2][4] = {}, aI[2][4] = {}, aH[2][4] = {};
        const uint4* __restrict__ fp = g_Wf + ((size_t)jc * KSTEPS) * 4 * 32 + lane;

        #pragma unroll 1
        for (int ks = 0; ks < KSTEPS; ks++) {
            uint4 fh  = fp[(size_t)ks * 128];        // {Rh, Zh}
            uint4 fih = fp[(size_t)ks * 128 + 32];   // {Ih, Hh}
            uint4 fl  = fp[(size_t)ks * 128 + 64];   // {Rl, Zl}
            uint4 fil = fp[(size_t)ks * 128 + 96];   // {Il, Hl}

            uint32_t h[2][4], l[2][4];
            LDSM4(h[0][0], h[0][1], h[0][2], h[0][3], ah[0] + ks * 32);
            LDSM4(h[1][0], h[1][1], h[1][2], h[1][3], ah[1] + ks * 32);
            LDSM4(l[0][0], l[0][1], l[0][2], l[0][3], al[0] + ks * 32);
            LDSM4(l[1][0], l[1][1], l[1][2], l[1][3], al[1] + ks * 32);

            const bool doI = (ks < 7);       // k < 112 (zero-padded past 100)
            const bool doH = (ks >= 6);      // k >= 96 (zero-padded before 100)

            // pass 1: Wh * xh
            #pragma unroll
            for (int t = 0; t < 2; t++) {
                MMA(aR[t], h[t], fh.x, fh.y);
                MMA(aZ[t], h[t], fh.z, fh.w);
                if (doI) MMA(aI[t], h[t], fih.x, fih.y);
                if (doH) MMA(aH[t], h[t], fih.z, fih.w);
            }
            // pass 2: Wh * xl
            #pragma unroll
            for (int t = 0; t < 2; t++) {
                MMA(aR[t], l[t], fh.x, fh.y);
                MMA(aZ[t], l[t], fh.z, fh.w);
                if (doI) MMA(aI[t], l[t], fih.x, fih.y);
                if (doH) MMA(aH[t], l[t], fih.z, fih.w);
            }
            // pass 3: Wl * xh
            #pragma unroll
            for (int t = 0; t < 2; t++) {
                MMA(aR[t], h[t], fl.x, fl.y);
                MMA(aZ[t], h[t], fl.z, fl.w);
                if (doI) MMA(aI[t], h[t], fil.x, fil.y);
                if (doH) MMA(aH[t], h[t], fil.z, fil.w);
            }
        }

        // ---- epilogue: both row tiles of this jc ----
        #pragma unroll
        for (int t = 0; t < 2; t++) {
            #pragma unroll
            for (int e = 0; e < 4; e++) {
                int lr = R + t * 16 + g + (e >> 1) * 8;   // local row
                int j  = jc * 8 + tg * 2 + (e & 1);       // output column
                int nid = s_nid[lr];
                if (nid >= 0 && j < MEM_DIM) {
                    float Rv = aR[t][e] + g_bias[j];
                    float Zv = aZ[t][e] + g_bias[JPAD + j];
                    float Iv = aI[t][e] + g_bias[2 * JPAD + j];
                    float Hv = aH[t][e] + g_bias[3 * JPAD + j];
                    int kk = MSG_DIM + j;
                    float h_old = __bfloat162float(xh[lr * XSTR + kk]) +
                                  __bfloat162float(xl[lr * XSTR + kk]);
                    float rg = 1.f / (1.f + expf(-Rv));
                    float zg = 1.f / (1.f + expf(-Zv));
                    float ng = tanhf(Iv + rg * Hv);
                    out[(size_t)nid * MEM_DIM + j] = (1.f - zg) * ng + zg * h_old;
                }
            }
        }
    }
}

// ---------------------------------------------------------------------------
extern "C" void kernel_launch(void* const* d_in, const int* in_sizes, int n_in,
                              void* d_out, int out_size) {
    const int*   node_ids    = (const int*)  d_in[0];
    const float* messages    = (const float*)d_in[1];
    const float* timestamps  = (const float*)d_in[2];
    const float* memory      = (const float*)d_in[3];
    const float* last_update = (const float*)d_in[4];
    const float* W_ih        = (const float*)d_in[5];
    const float* W_hh        = (const float*)d_in[6];
    const float* b_ih        = (const float*)d_in[7];
    const float* b_hh        = (const float*)d_in[8];
    float* out = (float*)d_out;

    const int       n_upd   = in_sizes[0];
    const long long n_nodes = in_sizes[4];
    const long long nmem    = n_nodes * (long long)MEM_DIM;

    cudaFuncSetAttribute(gru_mma_kernel,
                         cudaFuncAttributeMaxDynamicSharedMemorySize, SM_TOT);

    prep_kernel<<<(NFRAG + 255) / 256, 256>>>(W_ih, W_hh, b_ih, b_hh);

    {
        long long n4 = (nmem + 3) >> 2;
        copy_kernel<<<(unsigned)((n4 + 255) / 256), 256>>>(memory, out, nmem);
        long long n4b = (n_nodes + 3) >> 2;
        copy_kernel<<<(unsigned)((n4b + 255) / 256), 256>>>(last_update, out + nmem, n_nodes);
    }

    if (n_upd > 0) {
        gru_mma_kernel<<<(n_upd + MROWS - 1) / MROWS, NTH, SM_TOT>>>(
            node_ids, messages, timestamps, memory, out, n_upd, n_nodes);
    }
}

// round 13
// speedup vs baseline: 1.7401x; 1.0353x over previous
#include <cuda_runtime.h>
#include <cuda_bf16.h>
#include <math.h>
#include <stdint.h>

#define MSG_DIM 100
#define MEM_DIM 172
#define KDIM    272
#define JPAD    176
#define MROWS   64             // update rows per CTA
#define NTH     128
#define KSTEPS  17             // 272 / 16
#define NJC     22             // 176 / 8 col-chunks
#define XSTR    280            // bf16 elems per x row (560 B)
// fragment tiles: (jc, ks) x 4 pair-slots x 32 lanes of uint4
#define NFRAG   (NJC * KSTEPS * 4 * 32)

// ---------------- persistent scratch ----------------
// uint4 = two gate fragments: p=0:{Rh,Zh} p=1:{Ih,Hh} p=2:{Rl,Zl} p=3:{Il,Hl}
__device__ __align__(16) uint4 g_Wf[NFRAG];
__device__ float g_bias[4 * JPAD];   // br, bz, bi, bh

// ---------------- smem layout (bytes) ----------------
#define SM_NID 0
#define SM_TS  256
#define SM_XH  1024
#define SM_XL  (SM_XH + MROWS * XSTR * 2)     // 36864
#define SM_TOT (SM_XL + MROWS * XSTR * 2)     // 72704 -> 3 CTAs/SM

// ---------------- helpers ----------------
__device__ __forceinline__ uint32_t smem_u32(const void* p) {
    uint32_t a;
    asm("{ .reg .u64 t; cvta.to.shared.u64 t, %1; cvt.u32.u64 %0, t; }" : "=r"(a) : "l"(p));
    return a;
}
#define LDSM4(r0, r1, r2, r3, addr) \
    asm volatile("ldmatrix.sync.aligned.m8n8.x4.shared.b16 {%0,%1,%2,%3}, [%4];" \
                 : "=r"(r0), "=r"(r1), "=r"(r2), "=r"(r3) : "r"(addr))
#define MMA(d, a, b0, b1) \
    asm volatile("mma.sync.aligned.m16n8k16.row.col.f32.bf16.bf16.f32 " \
                 "{%0,%1,%2,%3}, {%4,%5,%6,%7}, {%8,%9}, {%0,%1,%2,%3};" \
                 : "+f"((d)[0]), "+f"((d)[1]), "+f"((d)[2]), "+f"((d)[3]) \
                 : "r"((a)[0]), "r"((a)[1]), "r"((a)[2]), "r"((a)[3]), \
                   "r"(b0), "r"(b1))

__device__ __forceinline__ float wval(int plane, int n, int k,
                                      const float* __restrict__ W_ih,
                                      const float* __restrict__ W_hh) {
    if (n >= MEM_DIM || k >= KDIM) return 0.f;
    if (plane == 0)
        return (k < MSG_DIM) ? W_ih[n * MSG_DIM + k]
                             : W_hh[n * MEM_DIM + (k - MSG_DIM)];
    if (plane == 1)
        return (k < MSG_DIM) ? W_ih[(MEM_DIM + n) * MSG_DIM + k]
                             : W_hh[(MEM_DIM + n) * MEM_DIM + (k - MSG_DIM)];
    if (plane == 2)
        return (k < MSG_DIM) ? W_ih[(2 * MEM_DIM + n) * MSG_DIM + k] : 0.f;
    return (k >= MSG_DIM) ? W_hh[(2 * MEM_DIM + n) * MEM_DIM + (k - MSG_DIM)] : 0.f;
}
__device__ __forceinline__ float bf_split(float w, int split) {
    __nv_bfloat16 h = __float2bfloat16(w);
    if (split == 0) return __bfloat162float(h);
    return w - __bfloat162float(h);
}
__device__ __forceinline__ uint32_t pack_bf(float a, float b) {
    __nv_bfloat162 v = __floats2bfloat162_rn(a, b);
    return *(uint32_t*)&v;                // low 16 = a
}

// ---------------------------------------------------------------------------
// Prep: build paired B fragments (uint4 = 2 gate frags) + bias. (R12 layout.)
// ---------------------------------------------------------------------------
__global__ void prep_kernel(const float* __restrict__ W_ih,
                            const float* __restrict__ W_hh,
                            const float* __restrict__ b_ih,
                            const float* __restrict__ b_hh) {
    int idx = blockIdx.x * blockDim.x + threadIdx.x;
    if (idx < NFRAG) {
        int lane = idx & 31;
        int rest = idx >> 5;
        int p    = rest & 3;
        rest >>= 2;
        int ks   = rest % KSTEPS;
        int jc   = rest / KSTEPS;
        int split  = p >> 1;               // 0 = hi, 1 = lo
        int planeA = (p & 1) * 2;          // 0 (R) or 2 (I)
        int planeB = planeA + 1;           // 1 (Z) or 3 (H)
        int n  = jc * 8 + (lane >> 2);
        int kb = ks * 16 + (lane & 3) * 2;
        float a00 = bf_split(wval(planeA, n, kb + 0, W_ih, W_hh), split);
        float a01 = bf_split(wval(planeA, n, kb + 1, W_ih, W_hh), split);
        float a10 = bf_split(wval(planeA, n, kb + 8, W_ih, W_hh), split);
        float a11 = bf_split(wval(planeA, n, kb + 9, W_ih, W_hh), split);
        float b00 = bf_split(wval(planeB, n, kb + 0, W_ih, W_hh), split);
        float b01 = bf_split(wval(planeB, n, kb + 1, W_ih, W_hh), split);
        float b10 = bf_split(wval(planeB, n, kb + 8, W_ih, W_hh), split);
        float b11 = bf_split(wval(planeB, n, kb + 9, W_ih, W_hh), split);
        g_Wf[idx] = make_uint4(pack_bf(a00, a01), pack_bf(a10, a11),
                               pack_bf(b00, b01), pack_bf(b10, b11));
    }
    if (idx < JPAD) {
        int j = idx;
        float br = 0.f, bz = 0.f, bi = 0.f, bh = 0.f;
        if (j < MEM_DIM) {
            br = b_ih[j]               + b_hh[j];
            bz = b_ih[MEM_DIM + j]     + b_hh[MEM_DIM + j];
            bi = b_ih[2 * MEM_DIM + j];
            bh = b_hh[2 * MEM_DIM + j];
        }
        g_bias[j]            = br;
        g_bias[JPAD + j]     = bz;
        g_bias[2 * JPAD + j] = bi;
        g_bias[3 * JPAD + j] = bh;
    }
}

// ---------------------------------------------------------------------------
// Passthrough copy (one float4/thread; near-HBM-peak).
// ---------------------------------------------------------------------------
__global__ void copy_kernel(const float* __restrict__ src, float* __restrict__ dst, long long n) {
    long long i = (long long)blockIdx.x * blockDim.x + threadIdx.x;
    long long n4 = n >> 2;
    if (i < n4) ((float4*)dst)[i] = ((const float4*)src)[i];
    long long tail = n & 3;
    if (i < tail) dst[n4 * 4 + i] = src[n4 * 4 + i];
}

// ---------------------------------------------------------------------------
// GRU via mma.sync bf16 3-pass split. CTA = 64 rows, 4 warps, 3 CTAs/SM.
// Each warp computes ALL 64 rows (4 m16 tiles) for its own jc subset
// (warps 0,1: 6 chunks; warps 2,3: 5). B fragments feed 4 MMAs each.
// ---------------------------------------------------------------------------
__global__ void __launch_bounds__(NTH, 3)
gru_mma_kernel(const int*   __restrict__ node_ids,
               const float* __restrict__ messages,
               const float* __restrict__ timestamps,
               const float* __restrict__ memory,
               float*       __restrict__ out,
               int n_upd, long long n_nodes)
{
    extern __shared__ __align__(16) char smc[];
    int*   s_nid = (int*)(smc + SM_NID);
    float* s_ts  = (float*)(smc + SM_TS);
    __nv_bfloat16* xh = (__nv_bfloat16*)(smc + SM_XH);
    __nv_bfloat16* xl = (__nv_bfloat16*)(smc + SM_XL);
    const uint32_t smb = smem_u32(smc);

    const int tid  = threadIdx.x;
    const int lane = tid & 31;
    const int wid  = tid >> 5;
    const int row0 = blockIdx.x * MROWS;

    if (tid < MROWS) {
        int r = row0 + tid;
        if (r < n_upd) { s_nid[tid] = node_ids[r]; s_ts[tid] = timestamps[r]; }
        else           { s_nid[tid] = -1;          s_ts[tid] = 0.f; }
    }
    __syncthreads();

    // last_update scatter
    if (tid < MROWS && s_nid[tid] >= 0)
        out[n_nodes * (long long)MEM_DIM + s_nid[tid]] = s_ts[tid];

    // ---- gather x rows, split to bf16 hi/lo ----
    for (int idx = tid; idx < MROWS * (XSTR / 2); idx += NTH) {
        int r  = idx / (XSTR / 2);
        int k  = (idx - r * (XSTR / 2)) * 2;
        float x0 = 0.f, x1 = 0.f;
        int nid = s_nid[r];
        if (nid >= 0) {
            long long grow = row0 + r;
            if (k < MSG_DIM)    x0 = messages[grow * MSG_DIM + k];
            else if (k < KDIM)  x0 = memory[(size_t)nid * MEM_DIM + (k - MSG_DIM)];
            int k1 = k + 1;
            if (k1 < MSG_DIM)   x1 = messages[grow * MSG_DIM + k1];
            else if (k1 < KDIM) x1 = memory[(size_t)nid * MEM_DIM + (k1 - MSG_DIM)];
        }
        __nv_bfloat16 h0 = __float2bfloat16(x0), h1 = __float2bfloat16(x1);
        float l0 = x0 - __bfloat162float(h0);
        float l1 = x1 - __bfloat162float(h1);
        ((uint32_t*)(xh))[idx] = ((uint32_t)__bfloat16_as_ushort(h1) << 16) |
                                 __bfloat16_as_ushort(h0);
        ((uint32_t*)(xl))[idx] = pack_bf(l0, l1);
    }
    __syncthreads();

    // ---- per-warp MMA main loop: 4 row tiles x own jc subset ----
    const int jc0 = (wid < 2) ? wid * 6 : 12 + (wid - 2) * 5;
    const int njw = (wid < 2) ? 6 : 5;
    const int g  = lane >> 2;
    const int tg = lane & 3;
    uint32_t ah[4], al[4];
    #pragma unroll
    for (int t = 0; t < 4; t++) {
        int rr = t * 16 + (lane & 15);
        ah[t] = smb + SM_XH + rr * (XSTR * 2) + ((lane >> 4) * 16);
        al[t] = smb + SM_XL + rr * (XSTR * 2) + ((lane >> 4) * 16);
    }

    for (int jcl = 0; jcl < njw; jcl++) {
        const int jc = jc0 + jcl;
        float aR[4][4] = {}, aZ[4][4] = {}, aI[4][4] = {}, aH[4][4] = {};
        const uint4* __restrict__ fp = g_Wf + ((size_t)jc * KSTEPS) * 4 * 32 + lane;

        #pragma unroll 1
        for (int ks = 0; ks < KSTEPS; ks++) {
            uint4 fh  = fp[(size_t)ks * 128];        // {Rh, Zh}
            uint4 fih = fp[(size_t)ks * 128 + 32];   // {Ih, Hh}
            uint4 fl  = fp[(size_t)ks * 128 + 64];   // {Rl, Zl}
            uint4 fil = fp[(size_t)ks * 128 + 96];   // {Il, Hl}

            const bool doI = (ks < 7);       // k < 112 (zero-padded past 100)
            const bool doH = (ks >= 6);      // k >= 96 (zero-padded before 100)

            #pragma unroll
            for (int t = 0; t < 4; t++) {
                uint32_t h[4], l[4];
                LDSM4(h[0], h[1], h[2], h[3], ah[t] + ks * 32);
                LDSM4(l[0], l[1], l[2], l[3], al[t] + ks * 32);

                // pass 1: Wh * xh
                MMA(aR[t], h, fh.x, fh.y);
                MMA(aZ[t], h, fh.z, fh.w);
                if (doI) MMA(aI[t], h, fih.x, fih.y);
                if (doH) MMA(aH[t], h, fih.z, fih.w);
                // pass 2: Wh * xl
                MMA(aR[t], l, fh.x, fh.y);
                MMA(aZ[t], l, fh.z, fh.w);
                if (doI) MMA(aI[t], l, fih.x, fih.y);
                if (doH) MMA(aH[t], l, fih.z, fih.w);
                // pass 3: Wl * xh
                MMA(aR[t], h, fl.x, fl.y);
                MMA(aZ[t], h, fl.z, fl.w);
                if (doI) MMA(aI[t], h, fil.x, fil.y);
                if (doH) MMA(aH[t], h, fil.z, fil.w);
            }
        }

        // ---- epilogue: all 4 row tiles of this jc ----
        #pragma unroll
        for (int t = 0; t < 4; t++) {
            #pragma unroll
            for (int e = 0; e < 4; e++) {
                int lr = t * 16 + g + (e >> 1) * 8;       // local row
                int j  = jc * 8 + tg * 2 + (e & 1);       // output column
                int nid = s_nid[lr];
                if (nid >= 0 && j < MEM_DIM) {
                    float Rv = aR[t][e] + g_bias[j];
                    float Zv = aZ[t][e] + g_bias[JPAD + j];
                    float Iv = aI[t][e] + g_bias[2 * JPAD + j];
                    float Hv = aH[t][e] + g_bias[3 * JPAD + j];
                    int kk = MSG_DIM + j;
                    float h_old = __bfloat162float(xh[lr * XSTR + kk]) +
                                  __bfloat162float(xl[lr * XSTR + kk]);
                    float rg = 1.f / (1.f + expf(-Rv));
                    float zg = 1.f / (1.f + expf(-Zv));
                    float ng = tanhf(Iv + rg * Hv);
                    out[(size_t)nid * MEM_DIM + j] = (1.f - zg) * ng + zg * h_old;
                }
            }
        }
    }
}

// ---------------------------------------------------------------------------
extern "C" void kernel_launch(void* const* d_in, const int* in_sizes, int n_in,
                              void* d_out, int out_size) {
    const int*   node_ids    = (const int*)  d_in[0];
    const float* messages    = (const float*)d_in[1];
    const float* timestamps  = (const float*)d_in[2];
    const float* memory      = (const float*)d_in[3];
    const float* last_update = (const float*)d_in[4];
    const float* W_ih        = (const float*)d_in[5];
    const float* W_hh        = (const float*)d_in[6];
    const float* b_ih        = (const float*)d_in[7];
    const float* b_hh        = (const float*)d_in[8];
    float* out = (float*)d_out;

    const int       n_upd   = in_sizes[0];
    const long long n_nodes = in_sizes[4];
    const long long nmem    = n_nodes * (long long)MEM_DIM;

    cudaFuncSetAttribute(gru_mma_kernel,
                         cudaFuncAttributeMaxDynamicSharedMemorySize, SM_TOT);

    prep_kernel<<<(NFRAG + 255) / 256, 256>>>(W_ih, W_hh, b_ih, b_hh);

    {
        long long n4 = (nmem + 3) >> 2;
        copy_kernel<<<(unsigned)((n4 + 255) / 256), 256>>>(memory, out, nmem);
        long long n4b = (n_nodes + 3) >> 2;
        copy_kernel<<<(unsigned)((n4b + 255) / 256), 256>>>(last_update, out + nmem, n_nodes);
    }

    if (n_upd > 0) {
        gru_mma_kernel<<<(n_upd + MROWS - 1) / MROWS, NTH, SM_TOT>>>(
            node_ids, messages, timestamps, memory, out, n_upd, n_nodes);
    }
}

// round 14
// speedup vs baseline: 1.9458x; 1.1182x over previous
#include <cuda_runtime.h>
#include <cuda_bf16.h>
#include <math.h>
#include <stdint.h>

#define MSG_DIM 100
#define MEM_DIM 172
#define KDIM    272
#define JPAD    176
#define MROWS   64             // update rows per CTA
#define NTH     128
#define KSTEPS  17             // 272 / 16
#define NJC     22             // 176 / 8 col-chunks
#define XSTR    280            // bf16 elems per x row (560 B)
// fragment tiles: (jc, ks) x 4 pair-slots x 32 lanes of uint4
#define NFRAG   (NJC * KSTEPS * 4 * 32)

// ---------------- persistent scratch ----------------
// uint4 = two gate fragments: p=0:{Rh,Zh} p=1:{Ih,Hh} p=2:{Rl,Zl} p=3:{Il,Hl}
__device__ __align__(16) uint4 g_Wf[NFRAG];
__device__ float g_bias[4 * JPAD];   // br, bz, bi, bh

// ---------------- smem layout (bytes) ----------------
#define SM_NID 0
#define SM_TS  256
#define SM_XH  1024
#define SM_XL  (SM_XH + MROWS * XSTR * 2)     // 36864
#define SM_TOT (SM_XL + MROWS * XSTR * 2)     // 72704 -> 3 CTAs/SM

// ---------------- helpers ----------------
__device__ __forceinline__ uint32_t smem_u32(const void* p) {
    uint32_t a;
    asm("{ .reg .u64 t; cvta.to.shared.u64 t, %1; cvt.u32.u64 %0, t; }" : "=r"(a) : "l"(p));
    return a;
}
#define LDSM4(r0, r1, r2, r3, addr) \
    asm volatile("ldmatrix.sync.aligned.m8n8.x4.shared.b16 {%0,%1,%2,%3}, [%4];" \
                 : "=r"(r0), "=r"(r1), "=r"(r2), "=r"(r3) : "r"(addr))
#define MMA(d, a, b0, b1) \
    asm volatile("mma.sync.aligned.m16n8k16.row.col.f32.bf16.bf16.f32 " \
                 "{%0,%1,%2,%3}, {%4,%5,%6,%7}, {%8,%9}, {%0,%1,%2,%3};" \
                 : "+f"((d)[0]), "+f"((d)[1]), "+f"((d)[2]), "+f"((d)[3]) \
                 : "r"((a)[0]), "r"((a)[1]), "r"((a)[2]), "r"((a)[3]), \
                   "r"(b0), "r"(b1))

__device__ __forceinline__ float wval(int plane, int n, int k,
                                      const float* __restrict__ W_ih,
                                      const float* __restrict__ W_hh) {
    if (n >= MEM_DIM || k >= KDIM) return 0.f;
    if (plane == 0)
        return (k < MSG_DIM) ? W_ih[n * MSG_DIM + k]
                             : W_hh[n * MEM_DIM + (k - MSG_DIM)];
    if (plane == 1)
        return (k < MSG_DIM) ? W_ih[(MEM_DIM + n) * MSG_DIM + k]
                             : W_hh[(MEM_DIM + n) * MEM_DIM + (k - MSG_DIM)];
    if (plane == 2)
        return (k < MSG_DIM) ? W_ih[(2 * MEM_DIM + n) * MSG_DIM + k] : 0.f;
    return (k >= MSG_DIM) ? W_hh[(2 * MEM_DIM + n) * MEM_DIM + (k - MSG_DIM)] : 0.f;
}
__device__ __forceinline__ float bf_split(float w, int split) {
    __nv_bfloat16 h = __float2bfloat16(w);
    if (split == 0) return __bfloat162float(h);
    return w - __bfloat162float(h);
}
__device__ __forceinline__ uint32_t pack_bf(float a, float b) {
    __nv_bfloat162 v = __floats2bfloat162_rn(a, b);
    return *(uint32_t*)&v;                // low 16 = a
}

// ---------------------------------------------------------------------------
// Prep: build paired B fragments (uint4 = 2 gate frags) + bias. (R12 layout.)
// ---------------------------------------------------------------------------
__global__ void prep_kernel(const float* __restrict__ W_ih,
                            const float* __restrict__ W_hh,
                            const float* __restrict__ b_ih,
                            const float* __restrict__ b_hh) {
    int idx = blockIdx.x * blockDim.x + threadIdx.x;
    if (idx < NFRAG) {
        int lane = idx & 31;
        int rest = idx >> 5;
        int p    = rest & 3;
        rest >>= 2;
        int ks   = rest % KSTEPS;
        int jc   = rest / KSTEPS;
        int split  = p >> 1;               // 0 = hi, 1 = lo
        int planeA = (p & 1) * 2;          // 0 (R) or 2 (I)
        int planeB = planeA + 1;           // 1 (Z) or 3 (H)
        int n  = jc * 8 + (lane >> 2);
        int kb = ks * 16 + (lane & 3) * 2;
        float a00 = bf_split(wval(planeA, n, kb + 0, W_ih, W_hh), split);
        float a01 = bf_split(wval(planeA, n, kb + 1, W_ih, W_hh), split);
        float a10 = bf_split(wval(planeA, n, kb + 8, W_ih, W_hh), split);
        float a11 = bf_split(wval(planeA, n, kb + 9, W_ih, W_hh), split);
        float b00 = bf_split(wval(planeB, n, kb + 0, W_ih, W_hh), split);
        float b01 = bf_split(wval(planeB, n, kb + 1, W_ih, W_hh), split);
        float b10 = bf_split(wval(planeB, n, kb + 8, W_ih, W_hh), split);
        float b11 = bf_split(wval(planeB, n, kb + 9, W_ih, W_hh), split);
        g_Wf[idx] = make_uint4(pack_bf(a00, a01), pack_bf(a10, a11),
                               pack_bf(b00, b01), pack_bf(b10, b11));
    }
    if (idx < JPAD) {
        int j = idx;
        float br = 0.f, bz = 0.f, bi = 0.f, bh = 0.f;
        if (j < MEM_DIM) {
            br = b_ih[j]               + b_hh[j];
            bz = b_ih[MEM_DIM + j]     + b_hh[MEM_DIM + j];
            bi = b_ih[2 * MEM_DIM + j];
            bh = b_hh[2 * MEM_DIM + j];
        }
        g_bias[j]            = br;
        g_bias[JPAD + j]     = bz;
        g_bias[2 * JPAD + j] = bi;
        g_bias[3 * JPAD + j] = bh;
    }
}

// ---------------------------------------------------------------------------
// Passthrough copy (one float4/thread; near-HBM-peak).
// ---------------------------------------------------------------------------
__global__ void copy_kernel(const float* __restrict__ src, float* __restrict__ dst, long long n) {
    long long i = (long long)blockIdx.x * blockDim.x + threadIdx.x;
    long long n4 = n >> 2;
    if (i < n4) ((float4*)dst)[i] = ((const float4*)src)[i];
    long long tail = n & 3;
    if (i < tail) dst[n4 * 4 + i] = src[n4 * 4 + i];
}

// ---------------------------------------------------------------------------
// GRU via mma.sync bf16 3-pass split. CTA = 64 rows, 4 warps, 3 CTAs/SM.
// Warp computes all 64 rows (4 m16 tiles) for its jc subset. Software
// pipelining: A fragments (LDSM) prefetched 1 row-tile ahead; B fragments
// (LDG.128) prefetched 1 k-step ahead.
// ---------------------------------------------------------------------------
__global__ void __launch_bounds__(NTH, 3)
gru_mma_kernel(const int*   __restrict__ node_ids,
               const float* __restrict__ messages,
               const float* __restrict__ timestamps,
               const float* __restrict__ memory,
               float*       __restrict__ out,
               int n_upd, long long n_nodes)
{
    extern __shared__ __align__(16) char smc[];
    int*   s_nid = (int*)(smc + SM_NID);
    float* s_ts  = (float*)(smc + SM_TS);
    __nv_bfloat16* xh = (__nv_bfloat16*)(smc + SM_XH);
    __nv_bfloat16* xl = (__nv_bfloat16*)(smc + SM_XL);
    const uint32_t smb = smem_u32(smc);

    const int tid  = threadIdx.x;
    const int lane = tid & 31;
    const int wid  = tid >> 5;
    const int row0 = blockIdx.x * MROWS;

    if (tid < MROWS) {
        int r = row0 + tid;
        if (r < n_upd) { s_nid[tid] = node_ids[r]; s_ts[tid] = timestamps[r]; }
        else           { s_nid[tid] = -1;          s_ts[tid] = 0.f; }
    }
    __syncthreads();

    // last_update scatter
    if (tid < MROWS && s_nid[tid] >= 0)
        out[n_nodes * (long long)MEM_DIM + s_nid[tid]] = s_ts[tid];

    // ---- gather x rows, split to bf16 hi/lo ----
    for (int idx = tid; idx < MROWS * (XSTR / 2); idx += NTH) {
        int r  = idx / (XSTR / 2);
        int k  = (idx - r * (XSTR / 2)) * 2;
        float x0 = 0.f, x1 = 0.f;
        int nid = s_nid[r];
        if (nid >= 0) {
            long long grow = row0 + r;
            if (k < MSG_DIM)    x0 = messages[grow * MSG_DIM + k];
            else if (k < KDIM)  x0 = memory[(size_t)nid * MEM_DIM + (k - MSG_DIM)];
            int k1 = k + 1;
            if (k1 < MSG_DIM)   x1 = messages[grow * MSG_DIM + k1];
            else if (k1 < KDIM) x1 = memory[(size_t)nid * MEM_DIM + (k1 - MSG_DIM)];
        }
        __nv_bfloat16 h0 = __float2bfloat16(x0), h1 = __float2bfloat16(x1);
        float l0 = x0 - __bfloat162float(h0);
        float l1 = x1 - __bfloat162float(h1);
        ((uint32_t*)(xh))[idx] = ((uint32_t)__bfloat16_as_ushort(h1) << 16) |
                                 __bfloat16_as_ushort(h0);
        ((uint32_t*)(xl))[idx] = pack_bf(l0, l1);
    }
    __syncthreads();

    // ---- per-warp MMA main loop: 4 row tiles x own jc subset ----
    const int jc0 = (wid < 2) ? wid * 6 : 12 + (wid - 2) * 5;
    const int njw = (wid < 2) ? 6 : 5;
    const int g  = lane >> 2;
    const int tg = lane & 3;
    uint32_t ah[4], al[4];
    #pragma unroll
    for (int t = 0; t < 4; t++) {
        int rr = t * 16 + (lane & 15);
        ah[t] = smb + SM_XH + rr * (XSTR * 2) + ((lane >> 4) * 16);
        al[t] = smb + SM_XL + rr * (XSTR * 2) + ((lane >> 4) * 16);
    }

    for (int jcl = 0; jcl < njw; jcl++) {
        const int jc = jc0 + jcl;
        float aR[4][4] = {}, aZ[4][4] = {}, aI[4][4] = {}, aH[4][4] = {};
        const uint4* __restrict__ fp = g_Wf + ((size_t)jc * KSTEPS) * 4 * 32 + lane;

        // ---- pipeline preload: B(ks=0), A(t=0, ks=0) ----
        uint4 fh  = fp[0];
        uint4 fih = fp[32];
        uint4 fl  = fp[64];
        uint4 fil = fp[96];
        uint32_t hA[4], lA[4];
        LDSM4(hA[0], hA[1], hA[2], hA[3], ah[0]);
        LDSM4(lA[0], lA[1], lA[2], lA[3], al[0]);

        #pragma unroll 1
        for (int ks = 0; ks < KSTEPS; ks++) {
            // prefetch B for ks+1 (clamped at the end; harmless reload)
            const int ksn = (ks + 1 < KSTEPS) ? ks + 1 : ks;
            uint4 fhN  = fp[(size_t)ksn * 128];
            uint4 fihN = fp[(size_t)ksn * 128 + 32];
            uint4 flN  = fp[(size_t)ksn * 128 + 64];
            uint4 filN = fp[(size_t)ksn * 128 + 96];

            const bool doI = (ks < 7);       // k < 112 (zero-padded past 100)
            const bool doH = (ks >= 6);      // k >= 96 (zero-padded before 100)

            #pragma unroll
            for (int t = 0; t < 4; t++) {
                // prefetch A for next tile (t+1, same ks) or (0, ks+1)
                const int tn  = (t + 1) & 3;
                const int ksA = (t == 3) ? ksn : ks;
                uint32_t hN[4], lN[4];
                LDSM4(hN[0], hN[1], hN[2], hN[3], ah[tn] + ksA * 32);
                LDSM4(lN[0], lN[1], lN[2], lN[3], al[tn] + ksA * 32);

                // pass 1: Wh * xh
                MMA(aR[t], hA, fh.x, fh.y);
                MMA(aZ[t], hA, fh.z, fh.w);
                if (doI) MMA(aI[t], hA, fih.x, fih.y);
                if (doH) MMA(aH[t], hA, fih.z, fih.w);
                // pass 2: Wh * xl
                MMA(aR[t], lA, fh.x, fh.y);
                MMA(aZ[t], lA, fh.z, fh.w);
                if (doI) MMA(aI[t], lA, fih.x, fih.y);
                if (doH) MMA(aH[t], lA, fih.z, fih.w);
                // pass 3: Wl * xh
                MMA(aR[t], hA, fl.x, fl.y);
                MMA(aZ[t], hA, fl.z, fl.w);
                if (doI) MMA(aI[t], hA, fil.x, fil.y);
                if (doH) MMA(aH[t], hA, fil.z, fil.w);

                #pragma unroll
                for (int q = 0; q < 4; q++) { hA[q] = hN[q]; lA[q] = lN[q]; }
            }
            fh = fhN; fih = fihN; fl = flN; fil = filN;
        }

        // ---- epilogue: all 4 row tiles of this jc ----
        #pragma unroll
        for (int t = 0; t < 4; t++) {
            #pragma unroll
            for (int e = 0; e < 4; e++) {
                int lr = t * 16 + g + (e >> 1) * 8;       // local row
                int j  = jc * 8 + tg * 2 + (e & 1);       // output column
                int nid = s_nid[lr];
                if (nid >= 0 && j < MEM_DIM) {
                    float Rv = aR[t][e] + g_bias[j];
                    float Zv = aZ[t][e] + g_bias[JPAD + j];
                    float Iv = aI[t][e] + g_bias[2 * JPAD + j];
                    float Hv = aH[t][e] + g_bias[3 * JPAD + j];
                    int kk = MSG_DIM + j;
                    float h_old = __bfloat162float(xh[lr * XSTR + kk]) +
                                  __bfloat162float(xl[lr * XSTR + kk]);
                    float rg = 1.f / (1.f + expf(-Rv));
                    float zg = 1.f / (1.f + expf(-Zv));
                    float ng = tanhf(Iv + rg * Hv);
                    out[(size_t)nid * MEM_DIM + j] = (1.f - zg) * ng + zg * h_old;
                }
            }
        }
    }
}

// ---------------------------------------------------------------------------
extern "C" void kernel_launch(void* const* d_in, const int* in_sizes, int n_in,
                              void* d_out, int out_size) {
    const int*   node_ids    = (const int*)  d_in[0];
    const float* messages    = (const float*)d_in[1];
    const float* timestamps  = (const float*)d_in[2];
    const float* memory      = (const float*)d_in[3];
    const float* last_update = (const float*)d_in[4];
    const float* W_ih        = (const float*)d_in[5];
    const float* W_hh        = (const float*)d_in[6];
    const float* b_ih        = (const float*)d_in[7];
    const float* b_hh        = (const float*)d_in[8];
    float* out = (float*)d_out;

    const int       n_upd   = in_sizes[0];
    const long long n_nodes = in_sizes[4];
    const long long nmem    = n_nodes * (long long)MEM_DIM;

    cudaFuncSetAttribute(gru_mma_kernel,
                         cudaFuncAttributeMaxDynamicSharedMemorySize, SM_TOT);

    prep_kernel<<<(NFRAG + 255) / 256, 256>>>(W_ih, W_hh, b_ih, b_hh);

    {
        long long n4 = (nmem + 3) >> 2;
        copy_kernel<<<(unsigned)((n4 + 255) / 256), 256>>>(memory, out, nmem);
        long long n4b = (n_nodes + 3) >> 2;
        copy_kernel<<<(unsigned)((n4b + 255) / 256), 256>>>(last_update, out + nmem, n_nodes);
    }

    if (n_upd > 0) {
        gru_mma_kernel<<<(n_upd + MROWS - 1) / MROWS, NTH, SM_TOT>>>(
            node_ids, messages, timestamps, memory, out, n_upd, n_nodes);
    }
}

// round 15
// speedup vs baseline: 2.1025x; 1.0805x over previous
#include <cuda_runtime.h>
#include <cuda_fp16.h>
#include <math.h>
#include <stdint.h>

#define MSG_DIM 100
#define MEM_DIM 172
#define KDIM    272
#define JPAD    176
#define MROWS   64             // update rows per CTA
#define NTH     128
#define KSTEPS  17             // 272 / 16
#define NJC     22             // 176 / 8 col-chunks
#define XSTR    280            // fp16 elems per x row (560 B)
// fragment tiles: (jc, ks) x 2 pair-slots x 32 lanes of uint4
#define NFRAG   (NJC * KSTEPS * 2 * 32)

// ---------------- persistent scratch ----------------
// uint4 = two gate fragments (fp16): p=0:{R,Z} p=1:{I,H}
__device__ __align__(16) uint4 g_Wf[NFRAG];
__device__ float g_bias[4 * JPAD];   // br, bz, bi, bh

// ---------------- smem layout (bytes) ----------------
#define SM_NID 0
#define SM_TS  256
#define SM_XH  1024
#define SM_XL  (SM_XH + MROWS * XSTR * 2)     // 36864
#define SM_TOT (SM_XL + MROWS * XSTR * 2)     // 72704 -> 3 CTAs/SM

// ---------------- helpers ----------------
__device__ __forceinline__ uint32_t smem_u32(const void* p) {
    uint32_t a;
    asm("{ .reg .u64 t; cvta.to.shared.u64 t, %1; cvt.u32.u64 %0, t; }" : "=r"(a) : "l"(p));
    return a;
}
#define LDSM4(r0, r1, r2, r3, addr) \
    asm volatile("ldmatrix.sync.aligned.m8n8.x4.shared.b16 {%0,%1,%2,%3}, [%4];" \
                 : "=r"(r0), "=r"(r1), "=r"(r2), "=r"(r3) : "r"(addr))
#define MMA(d, a, b0, b1) \
    asm volatile("mma.sync.aligned.m16n8k16.row.col.f32.f16.f16.f32 " \
                 "{%0,%1,%2,%3}, {%4,%5,%6,%7}, {%8,%9}, {%0,%1,%2,%3};" \
                 : "+f"((d)[0]), "+f"((d)[1]), "+f"((d)[2]), "+f"((d)[3]) \
                 : "r"((a)[0]), "r"((a)[1]), "r"((a)[2]), "r"((a)[3]), \
                   "r"(b0), "r"(b1))

__device__ __forceinline__ float wval(int plane, int n, int k,
                                      const float* __restrict__ W_ih,
                                      const float* __restrict__ W_hh) {
    if (n >= MEM_DIM || k >= KDIM) return 0.f;
    if (plane == 0)
        return (k < MSG_DIM) ? W_ih[n * MSG_DIM + k]
                             : W_hh[n * MEM_DIM + (k - MSG_DIM)];
    if (plane == 1)
        return (k < MSG_DIM) ? W_ih[(MEM_DIM + n) * MSG_DIM + k]
                             : W_hh[(MEM_DIM + n) * MEM_DIM + (k - MSG_DIM)];
    if (plane == 2)
        return (k < MSG_DIM) ? W_ih[(2 * MEM_DIM + n) * MSG_DIM + k] : 0.f;
    return (k >= MSG_DIM) ? W_hh[(2 * MEM_DIM + n) * MEM_DIM + (k - MSG_DIM)] : 0.f;
}
__device__ __forceinline__ uint32_t pack_h(float a, float b) {
    __half2 v = __floats2half2_rn(a, b);
    return *(uint32_t*)&v;                // low 16 = a
}

// ---------------------------------------------------------------------------
// Prep: build paired fp16 B fragments (uint4 = {R,Z} or {I,H}) + bias.
// Per-fragment mapping (validated R10): n = jc*8 + (lane>>2),
// kb = ks*16 + (lane&3)*2; b0 = pack(w[kb], w[kb+1]), b1 = pack(w[kb+8], w[kb+9]).
// ---------------------------------------------------------------------------
__global__ void prep_kernel(const float* __restrict__ W_ih,
                            const float* __restrict__ W_hh,
                            const float* __restrict__ b_ih,
                            const float* __restrict__ b_hh) {
    int idx = blockIdx.x * blockDim.x + threadIdx.x;
    if (idx < NFRAG) {
        int lane = idx & 31;
        int rest = idx >> 5;
        int p    = rest & 1;
        rest >>= 1;
        int ks   = rest % KSTEPS;
        int jc   = rest / KSTEPS;
        int planeA = p * 2;                // 0 (R) or 2 (I)
        int planeB = planeA + 1;           // 1 (Z) or 3 (H)
        int n  = jc * 8 + (lane >> 2);
        int kb = ks * 16 + (lane & 3) * 2;
        float a00 = wval(planeA, n, kb + 0, W_ih, W_hh);
        float a01 = wval(planeA, n, kb + 1, W_ih, W_hh);
        float a10 = wval(planeA, n, kb + 8, W_ih, W_hh);
        float a11 = wval(planeA, n, kb + 9, W_ih, W_hh);
        float b00 = wval(planeB, n, kb + 0, W_ih, W_hh);
        float b01 = wval(planeB, n, kb + 1, W_ih, W_hh);
        float b10 = wval(planeB, n, kb + 8, W_ih, W_hh);
        float b11 = wval(planeB, n, kb + 9, W_ih, W_hh);
        g_Wf[idx] = make_uint4(pack_h(a00, a01), pack_h(a10, a11),
                               pack_h(b00, b01), pack_h(b10, b11));
    }
    if (idx < JPAD) {
        int j = idx;
        float br = 0.f, bz = 0.f, bi = 0.f, bh = 0.f;
        if (j < MEM_DIM) {
            br = b_ih[j]               + b_hh[j];
            bz = b_ih[MEM_DIM + j]     + b_hh[MEM_DIM + j];
            bi = b_ih[2 * MEM_DIM + j];
            bh = b_hh[2 * MEM_DIM + j];
        }
        g_bias[j]            = br;
        g_bias[JPAD + j]     = bz;
        g_bias[2 * JPAD + j] = bi;
        g_bias[3 * JPAD + j] = bh;
    }
}

// ---------------------------------------------------------------------------
// Passthrough copy (one float4/thread; near-HBM-peak).
// ---------------------------------------------------------------------------
__global__ void copy_kernel(const float* __restrict__ src, float* __restrict__ dst, long long n) {
    long long i = (long long)blockIdx.x * blockDim.x + threadIdx.x;
    long long n4 = n >> 2;
    if (i < n4) ((float4*)dst)[i] = ((const float4*)src)[i];
    long long tail = n & 3;
    if (i < tail) dst[n4 * 4 + i] = src[n4 * 4 + i];
}

// ---------------------------------------------------------------------------
// GRU via mma.sync fp16 2-pass split (x = xh + xl, W single fp16).
// CTA = 64 rows, 4 warps, 3 CTAs/SM. Warp computes all 64 rows (4 m16 tiles)
// for its jc subset. A fragments prefetched 1 tile ahead; B 1 k-step ahead.
// ---------------------------------------------------------------------------
__global__ void __launch_bounds__(NTH, 3)
gru_mma_kernel(const int*   __restrict__ node_ids,
               const float* __restrict__ messages,
               const float* __restrict__ timestamps,
               const float* __restrict__ memory,
               float*       __restrict__ out,
               int n_upd, long long n_nodes)
{
    extern __shared__ __align__(16) char smc[];
    int*   s_nid = (int*)(smc + SM_NID);
    float* s_ts  = (float*)(smc + SM_TS);
    __half* xh = (__half*)(smc + SM_XH);
    __half* xl = (__half*)(smc + SM_XL);
    const uint32_t smb = smem_u32(smc);

    const int tid  = threadIdx.x;
    const int lane = tid & 31;
    const int wid  = tid >> 5;
    const int row0 = blockIdx.x * MROWS;

    if (tid < MROWS) {
        int r = row0 + tid;
        if (r < n_upd) { s_nid[tid] = node_ids[r]; s_ts[tid] = timestamps[r]; }
        else           { s_nid[tid] = -1;          s_ts[tid] = 0.f; }
    }
    __syncthreads();

    // last_update scatter
    if (tid < MROWS && s_nid[tid] >= 0)
        out[n_nodes * (long long)MEM_DIM + s_nid[tid]] = s_ts[tid];

    // ---- gather x rows, split to fp16 hi/lo ----
    for (int idx = tid; idx < MROWS * (XSTR / 2); idx += NTH) {
        int r  = idx / (XSTR / 2);
        int k  = (idx - r * (XSTR / 2)) * 2;
        float x0 = 0.f, x1 = 0.f;
        int nid = s_nid[r];
        if (nid >= 0) {
            long long grow = row0 + r;
            if (k < MSG_DIM)    x0 = messages[grow * MSG_DIM + k];
            else if (k < KDIM)  x0 = memory[(size_t)nid * MEM_DIM + (k - MSG_DIM)];
            int k1 = k + 1;
            if (k1 < MSG_DIM)   x1 = messages[grow * MSG_DIM + k1];
            else if (k1 < KDIM) x1 = memory[(size_t)nid * MEM_DIM + (k1 - MSG_DIM)];
        }
        __half h0 = __float2half_rn(x0), h1 = __float2half_rn(x1);
        float l0 = x0 - __half2float(h0);
        float l1 = x1 - __half2float(h1);
        ((uint32_t*)(xh))[idx] = ((uint32_t)__half_as_ushort(h1) << 16) |
                                 __half_as_ushort(h0);
        ((uint32_t*)(xl))[idx] = pack_h(l0, l1);
    }
    __syncthreads();

    // ---- per-warp MMA main loop: 4 row tiles x own jc subset ----
    const int jc0 = (wid < 2) ? wid * 6 : 12 + (wid - 2) * 5;
    const int njw = (wid < 2) ? 6 : 5;
    const int g  = lane >> 2;
    const int tg = lane & 3;
    uint32_t ah[4], al[4];
    #pragma unroll
    for (int t = 0; t < 4; t++) {
        int rr = t * 16 + (lane & 15);
        ah[t] = smb + SM_XH + rr * (XSTR * 2) + ((lane >> 4) * 16);
        al[t] = smb + SM_XL + rr * (XSTR * 2) + ((lane >> 4) * 16);
    }

    for (int jcl = 0; jcl < njw; jcl++) {
        const int jc = jc0 + jcl;
        float aR[4][4] = {}, aZ[4][4] = {}, aI[4][4] = {}, aH[4][4] = {};
        const uint4* __restrict__ fp = g_Wf + ((size_t)jc * KSTEPS) * 2 * 32 + lane;

        // ---- pipeline preload: B(ks=0), A(t=0, ks=0) ----
        uint4 fh  = fp[0];        // {R, Z}
        uint4 fih = fp[32];       // {I, H}
        uint32_t hA[4], lA[4];
        LDSM4(hA[0], hA[1], hA[2], hA[3], ah[0]);
        LDSM4(lA[0], lA[1], lA[2], lA[3], al[0]);

        #pragma unroll 1
        for (int ks = 0; ks < KSTEPS; ks++) {
            // prefetch B for ks+1 (clamped at the end; harmless reload)
            const int ksn = (ks + 1 < KSTEPS) ? ks + 1 : ks;
            uint4 fhN  = fp[(size_t)ksn * 64];
            uint4 fihN = fp[(size_t)ksn * 64 + 32];

            const bool doI = (ks < 7);       // k < 112 (zero-padded past 100)
            const bool doH = (ks >= 6);      // k >= 96 (zero-padded before 100)

            #pragma unroll
            for (int t = 0; t < 4; t++) {
                // prefetch A for next tile (t+1, same ks) or (0, ks+1)
                const int tn  = (t + 1) & 3;
                const int ksA = (t == 3) ? ksn : ks;
                uint32_t hN[4], lN[4];
                LDSM4(hN[0], hN[1], hN[2], hN[3], ah[tn] + ksA * 32);
                LDSM4(lN[0], lN[1], lN[2], lN[3], al[tn] + ksA * 32);

                // pass 1: W * xh
                MMA(aR[t], hA, fh.x, fh.y);
                MMA(aZ[t], hA, fh.z, fh.w);
                if (doI) MMA(aI[t], hA, fih.x, fih.y);
                if (doH) MMA(aH[t], hA, fih.z, fih.w);
                // pass 2: W * xl
                MMA(aR[t], lA, fh.x, fh.y);
                MMA(aZ[t], lA, fh.z, fh.w);
                if (doI) MMA(aI[t], lA, fih.x, fih.y);
                if (doH) MMA(aH[t], lA, fih.z, fih.w);

                #pragma unroll
                for (int q = 0; q < 4; q++) { hA[q] = hN[q]; lA[q] = lN[q]; }
            }
            fh = fhN; fih = fihN;
        }

        // ---- epilogue: all 4 row tiles of this jc ----
        #pragma unroll
        for (int t = 0; t < 4; t++) {
            #pragma unroll
            for (int e = 0; e < 4; e++) {
                int lr = t * 16 + g + (e >> 1) * 8;       // local row
                int j  = jc * 8 + tg * 2 + (e & 1);       // output column
                int nid = s_nid[lr];
                if (nid >= 0 && j < MEM_DIM) {
                    float Rv = aR[t][e] + g_bias[j];
                    float Zv = aZ[t][e] + g_bias[JPAD + j];
                    float Iv = aI[t][e] + g_bias[2 * JPAD + j];
                    float Hv = aH[t][e] + g_bias[3 * JPAD + j];
                    int kk = MSG_DIM + j;
                    float h_old = __half2float(xh[lr * XSTR + kk]) +
                                  __half2float(xl[lr * XSTR + kk]);
                    float rg = 1.f / (1.f + expf(-Rv));
                    float zg = 1.f / (1.f + expf(-Zv));
                    float ng = tanhf(Iv + rg * Hv);
                    out[(size_t)nid * MEM_DIM + j] = (1.f - zg) * ng + zg * h_old;
                }
            }
        }
    }
}

// ---------------------------------------------------------------------------
extern "C" void kernel_launch(void* const* d_in, const int* in_sizes, int n_in,
                              void* d_out, int out_size) {
    const int*   node_ids    = (const int*)  d_in[0];
    const float* messages    = (const float*)d_in[1];
    const float* timestamps  = (const float*)d_in[2];
    const float* memory      = (const float*)d_in[3];
    const float* last_update = (const float*)d_in[4];
    const float* W_ih        = (const float*)d_in[5];
    const float* W_hh        = (const float*)d_in[6];
    const float* b_ih        = (const float*)d_in[7];
    const float* b_hh        = (const float*)d_in[8];
    float* out = (float*)d_out;

    const int       n_upd   = in_sizes[0];
    const long long n_nodes = in_sizes[4];
    const long long nmem    = n_nodes * (long long)MEM_DIM;

    cudaFuncSetAttribute(gru_mma_kernel,
                         cudaFuncAttributeMaxDynamicSharedMemorySize, SM_TOT);

    prep_kernel<<<(NFRAG + 255) / 256, 256>>>(W_ih, W_hh, b_ih, b_hh);

    {
        long long n4 = (nmem + 3) >> 2;
        copy_kernel<<<(unsigned)((n4 + 255) / 256), 256>>>(memory, out, nmem);
        long long n4b = (n_nodes + 3) >> 2;
        copy_kernel<<<(unsigned)((n4b + 255) / 256), 256>>>(last_update, out + nmem, n_nodes);
    }

    if (n_upd > 0) {
        gru_mma_kernel<<<(n_upd + MROWS - 1) / MROWS, NTH, SM_TOT>>>(
            node_ids, messages, timestamps, memory, out, n_upd, n_nodes);
    }
}

// round 16
// speedup vs baseline: 2.6407x; 1.2560x over previous
#include <cuda_runtime.h>
#include <cuda_fp16.h>
#include <math.h>
#include <stdint.h>

#define MSG_DIM 100
#define MEM_DIM 172
#define KDIM    272
#define JPAD    176
#define MROWS   64             // update rows per CTA
#define NTH     128
#define KSTEPS  17             // 272 / 16
#define NJC     22             // 176 / 8 col-chunks
#define XSTR    280            // fp16 elems per x row (560 B)
// fragment tiles: (jc, ks) x 2 pair-slots x 32 lanes of uint4
#define NFRAG   (NJC * KSTEPS * 2 * 32)

// ---------------- persistent scratch ----------------
// uint4 = two gate fragments (fp16): p=0:{R,Z} p=1:{I,H}
__device__ __align__(16) uint4 g_Wf[NFRAG];
__device__ float g_bias[4 * JPAD];   // br, bz, bi, bh

// ---------------- smem layout (bytes) ----------------
#define SM_NID 0
#define SM_TS  256
#define SM_XH  1024
#define SM_TOT (SM_XH + MROWS * XSTR * 2)     // 36864 -> 4+ CTAs/SM

// ---------------- helpers ----------------
__device__ __forceinline__ uint32_t smem_u32(const void* p) {
    uint32_t a;
    asm("{ .reg .u64 t; cvta.to.shared.u64 t, %1; cvt.u32.u64 %0, t; }" : "=r"(a) : "l"(p));
    return a;
}
#define LDSM4(r0, r1, r2, r3, addr) \
    asm volatile("ldmatrix.sync.aligned.m8n8.x4.shared.b16 {%0,%1,%2,%3}, [%4];" \
                 : "=r"(r0), "=r"(r1), "=r"(r2), "=r"(r3) : "r"(addr))
#define MMA(d, a, b0, b1) \
    asm volatile("mma.sync.aligned.m16n8k16.row.col.f32.f16.f16.f32 " \
                 "{%0,%1,%2,%3}, {%4,%5,%6,%7}, {%8,%9}, {%0,%1,%2,%3};" \
                 : "+f"((d)[0]), "+f"((d)[1]), "+f"((d)[2]), "+f"((d)[3]) \
                 : "r"((a)[0]), "r"((a)[1]), "r"((a)[2]), "r"((a)[3]), \
                   "r"(b0), "r"(b1))

__device__ __forceinline__ float wval(int plane, int n, int k,
                                      const float* __restrict__ W_ih,
                                      const float* __restrict__ W_hh) {
    if (n >= MEM_DIM || k >= KDIM) return 0.f;
    if (plane == 0)
        return (k < MSG_DIM) ? W_ih[n * MSG_DIM + k]
                             : W_hh[n * MEM_DIM + (k - MSG_DIM)];
    if (plane == 1)
        return (k < MSG_DIM) ? W_ih[(MEM_DIM + n) * MSG_DIM + k]
                             : W_hh[(MEM_DIM + n) * MEM_DIM + (k - MSG_DIM)];
    if (plane == 2)
        return (k < MSG_DIM) ? W_ih[(2 * MEM_DIM + n) * MSG_DIM + k] : 0.f;
    return (k >= MSG_DIM) ? W_hh[(2 * MEM_DIM + n) * MEM_DIM + (k - MSG_DIM)] : 0.f;
}
__device__ __forceinline__ uint32_t pack_h(float a, float b) {
    __half2 v = __floats2half2_rn(a, b);
    return *(uint32_t*)&v;                // low 16 = a
}

// ---------------------------------------------------------------------------
// Prep: build paired fp16 B fragments (uint4 = {R,Z} or {I,H}) + bias.
// Per-fragment mapping (validated R10): n = jc*8 + (lane>>2),
// kb = ks*16 + (lane&3)*2; b0 = pack(w[kb], w[kb+1]), b1 = pack(w[kb+8], w[kb+9]).
// ---------------------------------------------------------------------------
__global__ void prep_kernel(const float* __restrict__ W_ih,
                            const float* __restrict__ W_hh,
                            const float* __restrict__ b_ih,
                            const float* __restrict__ b_hh) {
    int idx = blockIdx.x * blockDim.x + threadIdx.x;
    if (idx < NFRAG) {
        int lane = idx & 31;
        int rest = idx >> 5;
        int p    = rest & 1;
        rest >>= 1;
        int ks   = rest % KSTEPS;
        int jc   = rest / KSTEPS;
        int planeA = p * 2;                // 0 (R) or 2 (I)
        int planeB = planeA + 1;           // 1 (Z) or 3 (H)
        int n  = jc * 8 + (lane >> 2);
        int kb = ks * 16 + (lane & 3) * 2;
        float a00 = wval(planeA, n, kb + 0, W_ih, W_hh);
        float a01 = wval(planeA, n, kb + 1, W_ih, W_hh);
        float a10 = wval(planeA, n, kb + 8, W_ih, W_hh);
        float a11 = wval(planeA, n, kb + 9, W_ih, W_hh);
        float b00 = wval(planeB, n, kb + 0, W_ih, W_hh);
        float b01 = wval(planeB, n, kb + 1, W_ih, W_hh);
        float b10 = wval(planeB, n, kb + 8, W_ih, W_hh);
        float b11 = wval(planeB, n, kb + 9, W_ih, W_hh);
        g_Wf[idx] = make_uint4(pack_h(a00, a01), pack_h(a10, a11),
                               pack_h(b00, b01), pack_h(b10, b11));
    }
    if (idx < JPAD) {
        int j = idx;
        float br = 0.f, bz = 0.f, bi = 0.f, bh = 0.f;
        if (j < MEM_DIM) {
            br = b_ih[j]               + b_hh[j];
            bz = b_ih[MEM_DIM + j]     + b_hh[MEM_DIM + j];
            bi = b_ih[2 * MEM_DIM + j];
            bh = b_hh[2 * MEM_DIM + j];
        }
        g_bias[j]            = br;
        g_bias[JPAD + j]     = bz;
        g_bias[2 * JPAD + j] = bi;
        g_bias[3 * JPAD + j] = bh;
    }
}

// ---------------------------------------------------------------------------
// Passthrough copy (one float4/thread; near-HBM-peak).
// ---------------------------------------------------------------------------
__global__ void copy_kernel(const float* __restrict__ src, float* __restrict__ dst, long long n) {
    long long i = (long long)blockIdx.x * blockDim.x + threadIdx.x;
    long long n4 = n >> 2;
    if (i < n4) ((float4*)dst)[i] = ((const float4*)src)[i];
    long long tail = n & 3;
    if (i < tail) dst[n4 * 4 + i] = src[n4 * 4 + i];
}

// ---------------------------------------------------------------------------
// GRU via mma.sync fp16 single-pass (x and W both fp16; fp32 accumulate;
// h_old re-read fp32 from gmem in the epilogue for exact z*h_old).
// CTA = 64 rows, 4 warps, 4 CTAs/SM. Warp computes all 64 rows (4 m16 tiles)
// for its jc subset. A fragments prefetched 1 tile ahead; B 1 k-step ahead.
// ---------------------------------------------------------------------------
__global__ void __launch_bounds__(NTH, 4)
gru_mma_kernel(const int*   __restrict__ node_ids,
               const float* __restrict__ messages,
               const float* __restrict__ timestamps,
               const float* __restrict__ memory,
               float*       __restrict__ out,
               int n_upd, long long n_nodes)
{
    extern __shared__ __align__(16) char smc[];
    int*   s_nid = (int*)(smc + SM_NID);
    float* s_ts  = (float*)(smc + SM_TS);
    __half* xh = (__half*)(smc + SM_XH);
    const uint32_t smb = smem_u32(smc);

    const int tid  = threadIdx.x;
    const int lane = tid & 31;
    const int wid  = tid >> 5;
    const int row0 = blockIdx.x * MROWS;

    if (tid < MROWS) {
        int r = row0 + tid;
        if (r < n_upd) { s_nid[tid] = node_ids[r]; s_ts[tid] = timestamps[r]; }
        else           { s_nid[tid] = -1;          s_ts[tid] = 0.f; }
    }
    __syncthreads();

    // last_update scatter
    if (tid < MROWS && s_nid[tid] >= 0)
        out[n_nodes * (long long)MEM_DIM + s_nid[tid]] = s_ts[tid];

    // ---- gather x rows as fp16 ----
    for (int idx = tid; idx < MROWS * (XSTR / 2); idx += NTH) {
        int r  = idx / (XSTR / 2);
        int k  = (idx - r * (XSTR / 2)) * 2;
        float x0 = 0.f, x1 = 0.f;
        int nid = s_nid[r];
        if (nid >= 0) {
            long long grow = row0 + r;
            if (k < MSG_DIM)    x0 = messages[grow * MSG_DIM + k];
            else if (k < KDIM)  x0 = memory[(size_t)nid * MEM_DIM + (k - MSG_DIM)];
            int k1 = k + 1;
            if (k1 < MSG_DIM)   x1 = messages[grow * MSG_DIM + k1];
            else if (k1 < KDIM) x1 = memory[(size_t)nid * MEM_DIM + (k1 - MSG_DIM)];
        }
        ((uint32_t*)(xh))[idx] = pack_h(x0, x1);
    }
    __syncthreads();

    // ---- per-warp MMA main loop: 4 row tiles x own jc subset ----
    const int jc0 = (wid < 2) ? wid * 6 : 12 + (wid - 2) * 5;
    const int njw = (wid < 2) ? 6 : 5;
    const int g  = lane >> 2;
    const int tg = lane & 3;
    uint32_t ah[4];
    #pragma unroll
    for (int t = 0; t < 4; t++) {
        int rr = t * 16 + (lane & 15);
        ah[t] = smb + SM_XH + rr * (XSTR * 2) + ((lane >> 4) * 16);
    }

    for (int jcl = 0; jcl < njw; jcl++) {
        const int jc = jc0 + jcl;
        float aR[4][4] = {}, aZ[4][4] = {}, aI[4][4] = {}, aH[4][4] = {};
        const uint4* __restrict__ fp = g_Wf + ((size_t)jc * KSTEPS) * 2 * 32 + lane;

        // ---- pipeline preload: B(ks=0), A(t=0, ks=0) ----
        uint4 fh  = fp[0];        // {R, Z}
        uint4 fih = fp[32];       // {I, H}
        uint32_t hA[4];
        LDSM4(hA[0], hA[1], hA[2], hA[3], ah[0]);

        #pragma unroll 1
        for (int ks = 0; ks < KSTEPS; ks++) {
            // prefetch B for ks+1 (clamped at the end; harmless reload)
            const int ksn = (ks + 1 < KSTEPS) ? ks + 1 : ks;
            uint4 fhN  = fp[(size_t)ksn * 64];
            uint4 fihN = fp[(size_t)ksn * 64 + 32];

            const bool doI = (ks < 7);       // k < 112 (zero-padded past 100)
            const bool doH = (ks >= 6);      // k >= 96 (zero-padded before 100)

            #pragma unroll
            for (int t = 0; t < 4; t++) {
                // prefetch A for next tile (t+1, same ks) or (0, ks+1)
                const int tn  = (t + 1) & 3;
                const int ksA = (t == 3) ? ksn : ks;
                uint32_t hN[4];
                LDSM4(hN[0], hN[1], hN[2], hN[3], ah[tn] + ksA * 32);

                MMA(aR[t], hA, fh.x, fh.y);
                MMA(aZ[t], hA, fh.z, fh.w);
                if (doI) MMA(aI[t], hA, fih.x, fih.y);
                if (doH) MMA(aH[t], hA, fih.z, fih.w);

                #pragma unroll
                for (int q = 0; q < 4; q++) hA[q] = hN[q];
            }
            fh = fhN; fih = fihN;
        }

        // ---- epilogue: all 4 row tiles of this jc (h_old exact from gmem) ----
        #pragma unroll
        for (int t = 0; t < 4; t++) {
            #pragma unroll
            for (int e = 0; e < 4; e++) {
                int lr = t * 16 + g + (e >> 1) * 8;       // local row
                int j  = jc * 8 + tg * 2 + (e & 1);       // output column
                int nid = s_nid[lr];
                if (nid >= 0 && j < MEM_DIM) {
                    float Rv = aR[t][e] + g_bias[j];
                    float Zv = aZ[t][e] + g_bias[JPAD + j];
                    float Iv = aI[t][e] + g_bias[2 * JPAD + j];
                    float Hv = aH[t][e] + g_bias[3 * JPAD + j];
                    float h_old = memory[(size_t)nid * MEM_DIM + j];  // exact fp32
                    float rg = 1.f / (1.f + expf(-Rv));
                    float zg = 1.f / (1.f + expf(-Zv));
                    float ng = tanhf(Iv + rg * Hv);
                    out[(size_t)nid * MEM_DIM + j] = (1.f - zg) * ng + zg * h_old;
                }
            }
        }
    }
}

// ---------------------------------------------------------------------------
extern "C" void kernel_launch(void* const* d_in, const int* in_sizes, int n_in,
                              void* d_out, int out_size) {
    const int*   node_ids    = (const int*)  d_in[0];
    const float* messages    = (const float*)d_in[1];
    const float* timestamps  = (const float*)d_in[2];
    const float* memory      = (const float*)d_in[3];
    const float* last_update = (const float*)d_in[4];
    const float* W_ih        = (const float*)d_in[5];
    const float* W_hh        = (const float*)d_in[6];
    const float* b_ih        = (const float*)d_in[7];
    const float* b_hh        = (const float*)d_in[8];
    float* out = (float*)d_out;

    const int       n_upd   = in_sizes[0];
    const long long n_nodes = in_sizes[4];
    const long long nmem    = n_nodes * (long long)MEM_DIM;

    cudaFuncSetAttribute(gru_mma_kernel,
                         cudaFuncAttributeMaxDynamicSharedMemorySize, SM_TOT);

    prep_kernel<<<(NFRAG + 255) / 256, 256>>>(W_ih, W_hh, b_ih, b_hh);

    {
        long long n4 = (nmem + 3) >> 2;
        copy_kernel<<<(unsigned)((n4 + 255) / 256), 256>>>(memory, out, nmem);
        long long n4b = (n_nodes + 3) >> 2;
        copy_kernel<<<(unsigned)((n4b + 255) / 256), 256>>>(last_update, out + nmem, n_nodes);
    }

    if (n_upd > 0) {
        gru_mma_kernel<<<(n_upd + MROWS - 1) / MROWS, NTH, SM_TOT>>>(
            node_ids, messages, timestamps, memory, out, n_upd, n_nodes);
    }
}